// round 9
// baseline (speedup 1.0000x reference)
#include <cuda_runtime.h>
#include <stdint.h>
#include <math.h>

#define Bv 64
#define Sv 256
#define Ev 300
#define Hv 300
#define H2 600
#define G4 1200
#define Rv 512
#define NRELv 46
#define RELDv 50

#define LSTM_BLOCKS 60          // each block owns 5 fwd units + 5 bwd units
#define LSTM_THREADS 320

// lstm dynamic smem layout (floats)
#define SH_OFF 0                        // sH [300][64]
#define SW_OFF 19200                    // sW [2][300*20]
#define SG_OFF (19200 + 12000)          // sG [20][64]
#define SC_OFF (SG_OFF + 1280)          // sC [2][5*64]
#define LSTM_SMEM_BYTES ((SC_OFF + 640) * 4)

// mma gemm tile config
#define ASTR 136
#define BSTR 72

// ---------------- device scratch ----------------
__device__ float d_text[Bv * Sv * Ev];
__device__ float d_Xg[2 * Sv * Bv * G4];
__device__ float d_hseq[2 * Sv * Hv * Bv];
__device__ float d_to[Bv * Sv * H2];
__device__ float d_hid[Bv * Sv * H2];
__device__ float d_x1[Bv * Sv * H2];
__device__ float d_V[NRELv * G4];
__device__ float d_score[Bv * Rv];
__device__ float d_pwv[Bv * Sv];
__device__ float d_xsum[Bv * H2];
__device__ float d_attsc[Bv * Sv];
__device__ float d_alpha[Bv * Sv];
__device__ float d_ov[Bv * H2];
__device__ int d_tlen[Bv], d_alen[Bv], d_llen[Bv];
__device__ unsigned d_barr[2 * Sv];

__device__ __forceinline__ unsigned ld_acquire(const unsigned* p) {
    unsigned v;
    asm volatile("ld.acquire.gpu.global.u32 %0, [%1];" : "=r"(v) : "l"(p) : "memory");
    return v;
}

__device__ __forceinline__ void red_release_add(unsigned* p) {
    asm volatile("red.release.gpu.global.add.u32 [%0], 1;" :: "l"(p) : "memory");
}

__device__ __forceinline__ float to_tf32(float x) {
    uint32_t r;
    asm("cvt.rna.tf32.f32 %0, %1;" : "=r"(r) : "f"(x));
    return __uint_as_float(r);
}

// ---------------- barrier reset ----------------
__global__ void barr_reset() {
    int i = threadIdx.x;
    if (i < 2 * Sv) d_barr[i] = 0u;
}

// ---------------- lengths ----------------
__global__ void len_kernel(const int* __restrict__ ti, const int* __restrict__ ai,
                           const int* __restrict__ li) {
    int b = threadIdx.x;
    if (b >= Bv) return;
    int t = 0;
    for (int s = 0; s < Sv; s++) t += (ti[b * Sv + s] != 0);
    int a = 0;
    for (int s = 0; s < 4; s++) a += (ai[b * 4 + s] != 0);
    int l = 0;
    for (int s = 0; s < 64; s++) l += (li[b * 64 + s] != 0);
    d_tlen[b] = t;
    d_alen[b] = a;
    d_llen[b] = l;
}

// ---------------- embedding gather ----------------
__global__ void embed_kernel(const int* __restrict__ idx, const float* __restrict__ emb) {
    int i = blockIdx.x * 256 + threadIdx.x;
    if (i >= Bv * Sv * Ev) return;
    int e = i % Ev;
    int m = i / Ev;
    d_text[i] = emb[idx[m] * Ev + e];
}

// ---------------- tf32 MMA GEMM (unchanged from R7 best) ----------------
template <int EPI, bool BT, bool PW>
__global__ void __launch_bounds__(256, 3)
mma_gemm(const float* __restrict__ A, const float* __restrict__ Bm,
         const float* __restrict__ bias, float* __restrict__ C,
         int M, int N, int K) {
    __shared__ float As[16 * ASTR];
    __shared__ float Bs[16 * BSTR];

    const int m0 = blockIdx.y * 128;
    const int n0 = blockIdx.x * 64;
    const int tid = threadIdx.x;
    const int wid = tid >> 5;
    const int lane = tid & 31;
    const int grp = lane >> 2;
    const int tig = lane & 3;
    const int m_base = wid * 16;

    float c[8][4];
#pragma unroll
    for (int n = 0; n < 8; n++)
#pragma unroll
        for (int i = 0; i < 4; i++) c[n][i] = 0.f;

    const int a_m = tid >> 1;
    const int a_k4 = (tid & 1) * 4;
    float pwscale = 1.f;
    if (PW) pwscale = d_pwv[m0 + a_m];

    const int kend = (K + 15) & ~15;

    for (int k0 = 0; k0 < kend; k0 += 16) {
#pragma unroll
        for (int kk2 = 0; kk2 < 16; kk2 += 8) {
            int k = k0 + kk2 + a_k4;
            float4 av = make_float4(0.f, 0.f, 0.f, 0.f);
            if (k < K) av = *(const float4*)&A[(size_t)(m0 + a_m) * K + k];
            if (PW) { av.x *= pwscale; av.y *= pwscale; av.z *= pwscale; av.w *= pwscale; }
            As[(kk2 + a_k4 + 0) * ASTR + a_m] = to_tf32(av.x);
            As[(kk2 + a_k4 + 1) * ASTR + a_m] = to_tf32(av.y);
            As[(kk2 + a_k4 + 2) * ASTR + a_m] = to_tf32(av.z);
            As[(kk2 + a_k4 + 3) * ASTR + a_m] = to_tf32(av.w);
        }
        if (BT) {
            int n_l = tid >> 2;
            int kk = (tid & 3) * 4;
            int row = n0 + n_l;
            int k = k0 + kk;
            float4 bv = make_float4(0.f, 0.f, 0.f, 0.f);
            if (row < N && k < K) bv = *(const float4*)&Bm[(size_t)row * K + k];
            Bs[(kk + 0) * BSTR + n_l] = to_tf32(bv.x);
            Bs[(kk + 1) * BSTR + n_l] = to_tf32(bv.y);
            Bs[(kk + 2) * BSTR + n_l] = to_tf32(bv.z);
            Bs[(kk + 3) * BSTR + n_l] = to_tf32(bv.w);
        } else {
            int kk = tid >> 4;
            int n_l = (tid & 15) * 4;
            int k = k0 + kk;
#pragma unroll
            for (int i = 0; i < 4; i++) {
                int n = n0 + n_l + i;
                float v = (k < K && n < N) ? Bm[(size_t)k * N + n] : 0.f;
                Bs[kk * BSTR + n_l + i] = to_tf32(v);
            }
        }
        __syncthreads();

#pragma unroll
        for (int ksub = 0; ksub < 2; ksub++) {
            const int kb = ksub * 8;
            uint32_t a0 = __float_as_uint(As[(kb + tig) * ASTR + m_base + grp]);
            uint32_t a1 = __float_as_uint(As[(kb + tig) * ASTR + m_base + grp + 8]);
            uint32_t a2 = __float_as_uint(As[(kb + tig + 4) * ASTR + m_base + grp]);
            uint32_t a3 = __float_as_uint(As[(kb + tig + 4) * ASTR + m_base + grp + 8]);
#pragma unroll
            for (int n = 0; n < 8; n++) {
                uint32_t b0 = __float_as_uint(Bs[(kb + tig) * BSTR + n * 8 + grp]);
                uint32_t b1 = __float_as_uint(Bs[(kb + tig + 4) * BSTR + n * 8 + grp]);
                asm volatile(
                    "mma.sync.aligned.m16n8k8.row.col.f32.tf32.tf32.f32 "
                    "{%0,%1,%2,%3}, {%4,%5,%6,%7}, {%8,%9}, {%0,%1,%2,%3};"
                    : "+f"(c[n][0]), "+f"(c[n][1]), "+f"(c[n][2]), "+f"(c[n][3])
                    : "r"(a0), "r"(a1), "r"(a2), "r"(a3), "r"(b0), "r"(b1));
            }
        }
        __syncthreads();
    }

#pragma unroll
    for (int n = 0; n < 8; n++) {
        int col0 = n0 + n * 8 + 2 * tig;
#pragma unroll
        for (int half = 0; half < 2; half++) {
            int row = m0 + m_base + grp + half * 8;
            float v0 = c[n][half * 2 + 0];
            float v1 = c[n][half * 2 + 1];
            if (EPI == 0) {
                float b0 = bias ? bias[col0] : 0.f;
                float b1 = (bias && col0 + 1 < N) ? bias[col0 + 1] : 0.f;
                if (col0 < N) C[(size_t)row * N + col0] = v0 + b0;
                if (col0 + 1 < N) C[(size_t)row * N + col0 + 1] = v1 + b1;
            } else {
                int bb = row >> 8;
                int ss = row & 255;
                size_t base = (size_t)(ss * Bv + bb) * G4;
                if (col0 < N) C[base + col0] = v0 + bias[col0];
                if (col0 + 1 < N) C[base + col0 + 1] = v1 + bias[col0 + 1];
            }
        }
    }
}

// ---------------- persistent BiLSTM: interleaved dual-direction ----------------
// 60 blocks, 320 threads. Each block: 5 fwd + 5 bwd units. Per step: fwd phase
// then bwd phase; each direction's grid barrier resolves under the other's compute.
__global__ void __launch_bounds__(LSTM_THREADS, 1)
lstm_persist(const float* __restrict__ Wfh, const float* __restrict__ Wbh) {
    extern __shared__ float sm[];
    float* sH = sm + SH_OFF;   // [k][b] 300x64 (shared by both phases)
    float* sW = sm + SW_OFF;   // [d][300*20]
    float* sG = sm + SG_OFF;   // [jl][b]
    float* sC = sm + SC_OFF;   // [d][5*64]

    const int ub5 = blockIdx.x * 5;
    const int tid = threadIdx.x;

    // stage both directions' W slices once
    for (int idx = tid; idx < 2 * 20 * 300; idx += LSTM_THREADS) {
        int dd = idx / 6000;
        int rem = idx % 6000;
        int jl = rem / 300, k = rem % 300;
        int j = (jl / 5) * 300 + ub5 + (jl % 5);
        const float* W = dd ? Wbh : Wfh;
        sW[dd * 6000 + k * 20 + jl] = W[j * 300 + k];
    }
    sC[tid] = 0.f;
    sC[320 + tid] = 0.f;
    __syncthreads();

    const int jl = tid % 20;
    const int bq = tid / 20;        // 0..15
    const int b0 = bq * 4;
    const int j = (jl / 5) * 300 + ub5 + (jl % 5);
    const int u_l = tid >> 6;       // 0..4
    const int b_f = tid & 63;
    const unsigned nblk = (unsigned)LSTM_BLOCKS;

    // per-direction X prefetch registers
    float pxf[4], pxb[4];
    {
        const float* __restrict__ X0 = d_Xg + (size_t)0 * Bv * G4;                 // d=0, t=0
        const float* __restrict__ X1 = d_Xg + (size_t)(Sv + Sv - 1) * Bv * G4;     // d=1, t=Sv-1
#pragma unroll
        for (int i = 0; i < 4; i++) {
            pxf[i] = X0[(b0 + i) * G4 + j];
            pxb[i] = X1[(b0 + i) * G4 + j];
        }
    }

    for (int step = 0; step < Sv; step++) {
#pragma unroll 1
        for (int d = 0; d < 2; d++) {
            const int t_x = (d == 0) ? step : (Sv - 1 - step);
            float* px = (d == 0) ? pxf : pxb;

            // wait for this direction's previous-step barrier (should already be done:
            // the other direction's full phase ran since we arrived)
            if (step > 0) {
                const unsigned* ctr = &d_barr[d * Sv + step - 1];
                while (ld_acquire(ctr) < nblk) {}
            }

            // copy h_prev -> sH (contiguous 300*64 floats)
            if (step > 0) {
                const int t_hp = (d == 0) ? (step - 1) : (Sv - step);
                const float4* __restrict__ Hp =
                    (const float4*)(d_hseq + (size_t)(d * Sv + t_hp) * Hv * Bv);
                float4* sH4 = (float4*)sH;
#pragma unroll
                for (int i = 0; i < 15; i++)
                    sH4[tid + i * LSTM_THREADS] = Hp[tid + i * LSTM_THREADS];
            }
            __syncthreads();

            float acc0 = px[0], acc1 = px[1], acc2 = px[2], acc3 = px[3];
            if (step > 0) {
                const float* __restrict__ sWd = sW + d * 6000;
#pragma unroll 6
                for (int k = 0; k < 300; k++) {
                    float w = sWd[k * 20 + jl];
                    float4 h4 = *(const float4*)&sH[k * 64 + b0];
                    acc0 += w * h4.x;
                    acc1 += w * h4.y;
                    acc2 += w * h4.z;
                    acc3 += w * h4.w;
                }
            }
            sG[jl * 64 + b0 + 0] = acc0;
            sG[jl * 64 + b0 + 1] = acc1;
            sG[jl * 64 + b0 + 2] = acc2;
            sG[jl * 64 + b0 + 3] = acc3;
            __syncthreads();

            // finalize: 5 units x 64 batches
            {
                float gi = sG[(0 * 5 + u_l) * 64 + b_f];
                float gf = sG[(1 * 5 + u_l) * 64 + b_f];
                float gg = sG[(2 * 5 + u_l) * 64 + b_f];
                float go = sG[(3 * 5 + u_l) * 64 + b_f];
                float cp = sC[d * 320 + u_l * 64 + b_f];
                float si = 1.f / (1.f + expf(-gi));
                float sf = 1.f / (1.f + expf(-gf));
                float so = 1.f / (1.f + expf(-go));
                float cc = sf * cp + si * tanhf(gg);
                sC[d * 320 + u_l * 64 + b_f] = cc;
                float h = so * tanhf(cc);
                d_hseq[((size_t)(d * Sv + t_x) * Hv + ub5 + u_l) * 64 + b_f] = h;
            }

            // prefetch this direction's next X (hidden under other phase + barrier)
            if (step + 1 < Sv) {
                const int tn = (d == 0) ? (step + 1) : (Sv - 2 - step);
                const float* __restrict__ Xn = d_Xg + (size_t)(d * Sv + tn) * Bv * G4;
#pragma unroll
                for (int i = 0; i < 4; i++) px[i] = Xn[(b0 + i) * G4 + j];
            }

            // arrive: release orders the h stores; all threads' stores fenced by sync
            __syncthreads();
            if (tid == 0) red_release_add(&d_barr[d * Sv + step]);
        }
    }
}

// ---------------- assemble text_out ----------------
__global__ void assemble_to() {
    int i = blockIdx.x * 256 + threadIdx.x;
    if (i >= Bv * Sv * H2) return;
    int h = i % H2;
    int bs = i / H2;
    int s = bs % Sv;
    int b = bs / Sv;
    int dsel = (h >= Hv) ? 1 : 0;
    int u = h - dsel * Hv;
    d_to[i] = d_hseq[((size_t)(dsel * Sv + s) * Hv + u) * 64 + b];
}

// ---------------- V = bil_W @ rel_embed^T ----------------
__global__ void vprep(const float* __restrict__ bw, const float* __restrict__ re) {
    int r = blockIdx.x;
    for (int i = threadIdx.x; i < G4; i += 256) {
        float a = 0.f;
#pragma unroll
        for (int jj = 0; jj < RELDv; jj++) a += bw[i * RELDv + jj] * re[r * RELDv + jj];
        d_V[r * G4 + i] = a;
    }
}

// ---------------- relation scores ----------------
__global__ void relscore(const int* __restrict__ head, const int* __restrict__ behead,
                         const int* __restrict__ rel, const float* __restrict__ bilb) {
    int g = blockIdx.x * 8 + (threadIdx.x >> 5);
    int lane = threadIdx.x & 31;
    if (g >= Bv * Rv) return;
    int b = g / Rv;
    int rr = rel[g];
    float dotv = 0.f;
    if (rr != 0) {
        int h1 = head[g], h2 = behead[g];
        const float* __restrict__ n1 = d_to + (size_t)(b * Sv + h1) * H2;
        const float* __restrict__ n2 = d_to + (size_t)(b * Sv + h2) * H2;
        const float* __restrict__ V = d_V + rr * G4;
        for (int i = lane; i < H2; i += 32) dotv += n1[i] * V[i] + n2[i] * V[H2 + i];
    }
#pragma unroll
    for (int o = 16; o; o >>= 1) dotv += __shfl_down_sync(0xffffffffu, dotv, o);
    if (lane == 0) d_score[g] = 1.f / (1.f + expf(-(dotv + bilb[0])));
}

// ---------------- position weights ----------------
__global__ void pwv_kernel() {
    int b = blockIdx.x;
    int s = threadIdx.x;
    float tl = (float)d_tlen[b];
    float al = (float)d_alen[b];
    float l0 = (float)d_llen[b];
    float l1 = l0 + al - 1.f;
    float ctx = tl - al;
    float jf = (float)s;
    float w;
    if (jf < l0) w = 1.f - (l0 - jf) / ctx;
    else if (jf <= l1) w = 0.f;
    else if (jf < tl) w = 1.f - (jf - l1) / ctx;
    else w = 0.f;
    d_pwv[b * Sv + s] = w;
}

// ---------------- sparse GCN apply ----------------
__global__ void gcn_apply(const int* __restrict__ head, const int* __restrict__ behead,
                          const float* __restrict__ bias, float* __restrict__ out) {
    int bs = blockIdx.x;
    int b = bs >> 8;
    int s1 = bs & 255;
    const int* hd = head + b * Rv;
    int L = 0, Rr = Rv;
    while (L < Rr) { int m = (L + Rr) >> 1; if (hd[m] < s1) L = m + 1; else Rr = m; }
    int lo = L;
    Rr = Rv;
    while (L < Rr) { int m = (L + Rr) >> 1; if (hd[m] <= s1) L = m + 1; else Rr = m; }
    int hi = L;
    float den = 1.f;
    for (int r = lo; r < hi; r++) den += d_score[b * Rv + r];
    float inv = 1.f / den;
    for (int h = threadIdx.x; h < H2; h += 128) {
        float a = 0.f;
        for (int r = lo; r < hi; r++)
            a += d_score[b * Rv + r] * d_hid[(size_t)(b * Sv + behead[b * Rv + r]) * H2 + h];
        float v = a * inv + bias[h];
        out[(size_t)(b * Sv + s1) * H2 + h] = fmaxf(v, 0.f);
    }
}

// ---------------- attention ----------------
__global__ void xsum_kernel(const float* __restrict__ x) {
    int b = blockIdx.x;
    int h = threadIdx.x;
    if (h >= H2) return;
    int l0 = d_llen[b];
    int l1 = l0 + d_alen[b] - 1;
    if (l1 > Sv - 1) l1 = Sv - 1;
    float a = 0.f;
    for (int s = l0; s <= l1; s++) a += x[(size_t)(b * Sv + s) * H2 + h];
    d_xsum[b * H2 + h] = a;
}

__global__ void attscore() {
    int g = blockIdx.x * 8 + (threadIdx.x >> 5);
    int lane = threadIdx.x & 31;
    if (g >= Bv * Sv) return;
    int b = g >> 8;
    float a = 0.f;
    for (int i = lane; i < H2; i += 32) a += d_xsum[b * H2 + i] * d_to[(size_t)g * H2 + i];
#pragma unroll
    for (int o = 16; o; o >>= 1) a += __shfl_down_sync(0xffffffffu, a, o);
    if (lane == 0) d_attsc[g] = a;
}

__global__ void softmax_kernel() {
    __shared__ float red[256];
    int b = blockIdx.x;
    int tid = threadIdx.x;
    float v = d_attsc[b * Sv + tid];
    red[tid] = v;
    __syncthreads();
    for (int o = 128; o; o >>= 1) {
        if (tid < o) red[tid] = fmaxf(red[tid], red[tid + o]);
        __syncthreads();
    }
    float smax = red[0];
    __syncthreads();
    float e = expf(v - smax);
    red[tid] = e;
    __syncthreads();
    for (int o = 128; o; o >>= 1) {
        if (tid < o) red[tid] += red[tid + o];
        __syncthreads();
    }
    d_alpha[b * Sv + tid] = e / red[0];
}

__global__ void outvec_kernel() {
    int b = blockIdx.x;
    int h = threadIdx.x;
    if (h >= H2) return;
    float a = 0.f;
    for (int s = 0; s < Sv; s++) a += d_alpha[b * Sv + s] * d_to[(size_t)(b * Sv + s) * H2 + h];
    d_ov[b * H2 + h] = a;
}

__global__ void final_fc(const float* __restrict__ fcW, const float* __restrict__ fcb,
                         float* __restrict__ out) {
    int b = blockIdx.x;
    int p = threadIdx.x >> 5;
    int lane = threadIdx.x & 31;
    if (p >= 3) return;
    float a = 0.f;
    for (int h = lane; h < H2; h += 32) a += d_ov[b * H2 + h] * fcW[h * 3 + p];
#pragma unroll
    for (int o = 16; o; o >>= 1) a += __shfl_down_sync(0xffffffffu, a, o);
    if (lane == 0) out[b * 3 + p] = a + fcb[p];
}

// ---------------- launch ----------------
extern "C" void kernel_launch(void* const* d_in, const int* in_sizes, int n_in,
                              void* d_out, int out_size) {
    const int* text_indices = (const int*)d_in[0];
    const int* aspect_indices = (const int*)d_in[1];
    const int* left_indices = (const int*)d_in[2];
    const int* head_vector = (const int*)d_in[4];
    const int* behead_vector = (const int*)d_in[5];
    const int* relation_vector = (const int*)d_in[6];
    const float* embed_table = (const float*)d_in[7];
    const float* rel_embed = (const float*)d_in[8];
    const float* Wf_ih = (const float*)d_in[9];
    const float* Wf_hh = (const float*)d_in[10];
    const float* bf = (const float*)d_in[11];
    const float* Wb_ih = (const float*)d_in[12];
    const float* Wb_hh = (const float*)d_in[13];
    const float* bb = (const float*)d_in[14];
    const float* bil_W = (const float*)d_in[15];
    const float* bil_b = (const float*)d_in[16];
    const float* gc1_W = (const float*)d_in[17];
    const float* gc1_b = (const float*)d_in[18];
    const float* gc2_W = (const float*)d_in[19];
    const float* gc2_b = (const float*)d_in[20];
    const float* fc_W = (const float*)d_in[21];
    const float* fc_b = (const float*)d_in[22];
    float* out = (float*)d_out;

    float* p_text;  cudaGetSymbolAddress((void**)&p_text, d_text);
    float* p_Xg;    cudaGetSymbolAddress((void**)&p_Xg, d_Xg);
    float* p_to;    cudaGetSymbolAddress((void**)&p_to, d_to);
    float* p_hid;   cudaGetSymbolAddress((void**)&p_hid, d_hid);
    float* p_x1;    cudaGetSymbolAddress((void**)&p_x1, d_x1);

    cudaFuncSetAttribute(lstm_persist, cudaFuncAttributeMaxDynamicSharedMemorySize,
                         LSTM_SMEM_BYTES);

    len_kernel<<<1, 64>>>(text_indices, aspect_indices, left_indices);
    embed_kernel<<<(Bv * Sv * Ev + 255) / 256, 256>>>(text_indices, embed_table);

    {
        dim3 g((G4 + 63) / 64, (Bv * Sv) / 128);
        mma_gemm<1, true, false><<<g, 256>>>(p_text, Wf_ih, bf, p_Xg, Bv * Sv, G4, Ev);
        mma_gemm<1, true, false><<<g, 256>>>(p_text, Wb_ih, bb,
                                             p_Xg + (size_t)Sv * Bv * G4, Bv * Sv, G4, Ev);
    }

    barr_reset<<<1, 512>>>();
    lstm_persist<<<LSTM_BLOCKS, LSTM_THREADS, LSTM_SMEM_BYTES>>>(Wf_hh, Wb_hh);

    assemble_to<<<(Bv * Sv * H2 + 255) / 256, 256>>>();

    vprep<<<NRELv, 256>>>(bil_W, rel_embed);
    relscore<<<(Bv * Rv) / 8, 256>>>(head_vector, behead_vector, relation_vector, bil_b);

    pwv_kernel<<<Bv, Sv>>>();

    {
        dim3 g((H2 + 63) / 64, (Bv * Sv) / 128);
        mma_gemm<0, false, true><<<g, 256>>>(p_to, gc1_W, nullptr, p_hid, Bv * Sv, H2, H2);
    }
    gcn_apply<<<Bv * Sv, 128>>>(head_vector, behead_vector, gc1_b, p_x1);

    {
        dim3 g((H2 + 63) / 64, (Bv * Sv) / 128);
        mma_gemm<0, false, true><<<g, 256>>>(p_x1, gc2_W, nullptr, p_hid, Bv * Sv, H2, H2);
    }
    gcn_apply<<<Bv * Sv, 128>>>(head_vector, behead_vector, gc2_b, p_x1);

    xsum_kernel<<<Bv, 640>>>(p_x1);
    attscore<<<(Bv * Sv) / 8, 256>>>();
    softmax_kernel<<<Bv, 256>>>();
    outvec_kernel<<<Bv, 640>>>();
    final_fc<<<Bv, 96>>>(fc_W, fc_b, out);

    (void)in_sizes; (void)n_in; (void)out_size;
}

// round 10
// speedup vs baseline: 1.2668x; 1.2668x over previous
#include <cuda_runtime.h>
#include <stdint.h>
#include <math.h>

#define Bv 64
#define Sv 256
#define Ev 300
#define Hv 300
#define H2 600
#define G4 1200
#define Rv 512
#define NRELv 46
#define RELDv 50

#define LSTM_BLOCKS_PER_DIR 60
#define LSTM_THREADS 320

// lstm dynamic smem layout (floats)
#define SH_OFF 0                        // sH [300][64]
#define SW_OFF 19200                    // sW2 [300][20][2] duplicated pairs
#define SG_OFF (19200 + 12000)          // sG [20][64]
#define SC_OFF (SG_OFF + 1280)          // sC [5][64]
#define LSTM_SMEM_BYTES ((SC_OFF + 320) * 4)

// mma gemm tile config
#define ASTR 136
#define BSTR 72

// ---------------- device scratch ----------------
__device__ float d_text[Bv * Sv * Ev];
__device__ float d_Xg[2 * Sv * Bv * G4];
__device__ float d_hseq[2 * Sv * Hv * Bv];
__device__ float d_to[Bv * Sv * H2];
__device__ float d_hid[Bv * Sv * H2];
__device__ float d_x1[Bv * Sv * H2];
__device__ float d_V[NRELv * G4];
__device__ float d_score[Bv * Rv];
__device__ float d_pwv[Bv * Sv];
__device__ float d_xsum[Bv * H2];
__device__ float d_attsc[Bv * Sv];
__device__ float d_alpha[Bv * Sv];
__device__ float d_ov[Bv * H2];
__device__ int d_tlen[Bv], d_alen[Bv], d_llen[Bv];
__device__ unsigned d_barr[2 * Sv];

__device__ __forceinline__ unsigned ld_acquire(const unsigned* p) {
    unsigned v;
    asm volatile("ld.acquire.gpu.global.u32 %0, [%1];" : "=r"(v) : "l"(p) : "memory");
    return v;
}

__device__ __forceinline__ float to_tf32(float x) {
    uint32_t r;
    asm("cvt.rna.tf32.f32 %0, %1;" : "=r"(r) : "f"(x));
    return __uint_as_float(r);
}

// ---------------- barrier reset ----------------
__global__ void barr_reset() {
    int i = threadIdx.x;
    if (i < 2 * Sv) d_barr[i] = 0u;
}

// ---------------- lengths ----------------
__global__ void len_kernel(const int* __restrict__ ti, const int* __restrict__ ai,
                           const int* __restrict__ li) {
    int b = threadIdx.x;
    if (b >= Bv) return;
    int t = 0;
    for (int s = 0; s < Sv; s++) t += (ti[b * Sv + s] != 0);
    int a = 0;
    for (int s = 0; s < 4; s++) a += (ai[b * 4 + s] != 0);
    int l = 0;
    for (int s = 0; s < 64; s++) l += (li[b * 64 + s] != 0);
    d_tlen[b] = t;
    d_alen[b] = a;
    d_llen[b] = l;
}

// ---------------- embedding gather ----------------
__global__ void embed_kernel(const int* __restrict__ idx, const float* __restrict__ emb) {
    int i = blockIdx.x * 256 + threadIdx.x;
    if (i >= Bv * Sv * Ev) return;
    int e = i % Ev;
    int m = i / Ev;
    d_text[i] = emb[idx[m] * Ev + e];
}

// ---------------- tf32 MMA GEMM (R7 proven) ----------------
template <int EPI, bool BT, bool PW>
__global__ void __launch_bounds__(256, 3)
mma_gemm(const float* __restrict__ A, const float* __restrict__ Bm,
         const float* __restrict__ bias, float* __restrict__ C,
         int M, int N, int K) {
    __shared__ float As[16 * ASTR];
    __shared__ float Bs[16 * BSTR];

    const int m0 = blockIdx.y * 128;
    const int n0 = blockIdx.x * 64;
    const int tid = threadIdx.x;
    const int wid = tid >> 5;
    const int lane = tid & 31;
    const int grp = lane >> 2;
    const int tig = lane & 3;
    const int m_base = wid * 16;

    float c[8][4];
#pragma unroll
    for (int n = 0; n < 8; n++)
#pragma unroll
        for (int i = 0; i < 4; i++) c[n][i] = 0.f;

    const int a_m = tid >> 1;
    const int a_k4 = (tid & 1) * 4;
    float pwscale = 1.f;
    if (PW) pwscale = d_pwv[m0 + a_m];

    const int kend = (K + 15) & ~15;

    for (int k0 = 0; k0 < kend; k0 += 16) {
#pragma unroll
        for (int kk2 = 0; kk2 < 16; kk2 += 8) {
            int k = k0 + kk2 + a_k4;
            float4 av = make_float4(0.f, 0.f, 0.f, 0.f);
            if (k < K) av = *(const float4*)&A[(size_t)(m0 + a_m) * K + k];
            if (PW) { av.x *= pwscale; av.y *= pwscale; av.z *= pwscale; av.w *= pwscale; }
            As[(kk2 + a_k4 + 0) * ASTR + a_m] = to_tf32(av.x);
            As[(kk2 + a_k4 + 1) * ASTR + a_m] = to_tf32(av.y);
            As[(kk2 + a_k4 + 2) * ASTR + a_m] = to_tf32(av.z);
            As[(kk2 + a_k4 + 3) * ASTR + a_m] = to_tf32(av.w);
        }
        if (BT) {
            int n_l = tid >> 2;
            int kk = (tid & 3) * 4;
            int row = n0 + n_l;
            int k = k0 + kk;
            float4 bv = make_float4(0.f, 0.f, 0.f, 0.f);
            if (row < N && k < K) bv = *(const float4*)&Bm[(size_t)row * K + k];
            Bs[(kk + 0) * BSTR + n_l] = to_tf32(bv.x);
            Bs[(kk + 1) * BSTR + n_l] = to_tf32(bv.y);
            Bs[(kk + 2) * BSTR + n_l] = to_tf32(bv.z);
            Bs[(kk + 3) * BSTR + n_l] = to_tf32(bv.w);
        } else {
            int kk = tid >> 4;
            int n_l = (tid & 15) * 4;
            int k = k0 + kk;
#pragma unroll
            for (int i = 0; i < 4; i++) {
                int n = n0 + n_l + i;
                float v = (k < K && n < N) ? Bm[(size_t)k * N + n] : 0.f;
                Bs[kk * BSTR + n_l + i] = to_tf32(v);
            }
        }
        __syncthreads();

#pragma unroll
        for (int ksub = 0; ksub < 2; ksub++) {
            const int kb = ksub * 8;
            uint32_t a0 = __float_as_uint(As[(kb + tig) * ASTR + m_base + grp]);
            uint32_t a1 = __float_as_uint(As[(kb + tig) * ASTR + m_base + grp + 8]);
            uint32_t a2 = __float_as_uint(As[(kb + tig + 4) * ASTR + m_base + grp]);
            uint32_t a3 = __float_as_uint(As[(kb + tig + 4) * ASTR + m_base + grp + 8]);
#pragma unroll
            for (int n = 0; n < 8; n++) {
                uint32_t b0 = __float_as_uint(Bs[(kb + tig) * BSTR + n * 8 + grp]);
                uint32_t b1 = __float_as_uint(Bs[(kb + tig + 4) * BSTR + n * 8 + grp]);
                asm volatile(
                    "mma.sync.aligned.m16n8k8.row.col.f32.tf32.tf32.f32 "
                    "{%0,%1,%2,%3}, {%4,%5,%6,%7}, {%8,%9}, {%0,%1,%2,%3};"
                    : "+f"(c[n][0]), "+f"(c[n][1]), "+f"(c[n][2]), "+f"(c[n][3])
                    : "r"(a0), "r"(a1), "r"(a2), "r"(a3), "r"(b0), "r"(b1));
            }
        }
        __syncthreads();
    }

#pragma unroll
    for (int n = 0; n < 8; n++) {
        int col0 = n0 + n * 8 + 2 * tig;
#pragma unroll
        for (int half = 0; half < 2; half++) {
            int row = m0 + m_base + grp + half * 8;
            float v0 = c[n][half * 2 + 0];
            float v1 = c[n][half * 2 + 1];
            if (EPI == 0) {
                float b0 = bias ? bias[col0] : 0.f;
                float b1 = (bias && col0 + 1 < N) ? bias[col0 + 1] : 0.f;
                if (col0 < N) C[(size_t)row * N + col0] = v0 + b0;
                if (col0 + 1 < N) C[(size_t)row * N + col0 + 1] = v1 + b1;
            } else {
                int bb = row >> 8;
                int ss = row & 255;
                size_t base = (size_t)(ss * Bv + bb) * G4;
                if (col0 < N) C[base + col0] = v0 + bias[col0];
                if (col0 + 1 < N) C[base + col0 + 1] = v1 + bias[col0 + 1];
            }
        }
    }
}

// ---------------- persistent BiLSTM (R7 structure + f32x2 inner loop) ----------------
__global__ void __launch_bounds__(LSTM_THREADS, 1)
lstm_persist(const float* __restrict__ Wfh, const float* __restrict__ Wbh) {
    extern __shared__ float sm[];
    float* sH = sm + SH_OFF;    // [k][b] 300x64
    float* sW2 = sm + SW_OFF;   // [k][jl][2] duplicated (w,w) pairs
    float* sG = sm + SG_OFF;    // [jl][b]
    float* sC = sm + SC_OFF;    // [u][b]

    const int d = blockIdx.x / LSTM_BLOCKS_PER_DIR;
    const int ub5 = (blockIdx.x % LSTM_BLOCKS_PER_DIR) * 5;
    const float* __restrict__ W = (d == 0) ? Wfh : Wbh;
    const int tid = threadIdx.x;

    for (int idx = tid; idx < 20 * 300; idx += LSTM_THREADS) {
        int jl = idx / 300, k = idx % 300;
        int j = (jl / 5) * 300 + ub5 + (jl % 5);
        float w = W[j * 300 + k];
        sW2[(k * 20 + jl) * 2 + 0] = w;
        sW2[(k * 20 + jl) * 2 + 1] = w;
    }
    sC[tid] = 0.f;
    __syncthreads();

    const int jl = tid % 20;
    const int bq = tid / 20;
    const int b0 = bq * 4;
    const int j = (jl / 5) * 300 + ub5 + (jl % 5);
    const int u_l = tid >> 6;
    const int b_f = tid & 63;
    const unsigned nblk = (unsigned)LSTM_BLOCKS_PER_DIR;

    float px0, px1, px2, px3;
    {
        const int t0 = (d == 0) ? 0 : (Sv - 1);
        const float* __restrict__ Xb = d_Xg + (size_t)(d * Sv + t0) * Bv * G4;
        px0 = Xb[(b0 + 0) * G4 + j];
        px1 = Xb[(b0 + 1) * G4 + j];
        px2 = Xb[(b0 + 2) * G4 + j];
        px3 = Xb[(b0 + 3) * G4 + j];
    }

    for (int step = 0; step < Sv; step++) {
        const int t_x = (d == 0) ? step : (Sv - 1 - step);

        unsigned long long acc01, acc23;
        asm("mov.b64 %0, {%1,%2};" : "=l"(acc01) : "f"(px0), "f"(px1));
        asm("mov.b64 %0, {%1,%2};" : "=l"(acc23) : "f"(px2), "f"(px3));

        if (step > 0) {
            const int t_hp = (d == 0) ? (step - 1) : (Sv - step);
            const float4* __restrict__ Hp =
                (const float4*)(d_hseq + (size_t)(d * Sv + t_hp) * Hv * Bv);
            float4* sH4 = (float4*)sH;
#pragma unroll
            for (int i = 0; i < 15; i++)
                sH4[tid + i * LSTM_THREADS] = Hp[tid + i * LSTM_THREADS];
            __syncthreads();

            const unsigned long long* __restrict__ sWp =
                (const unsigned long long*)(sW2) + jl;
#pragma unroll 6
            for (int k = 0; k < 300; k++) {
                unsigned long long w2 = sWp[k * 20];
                unsigned long long h01 = *(const unsigned long long*)&sH[k * 64 + b0];
                unsigned long long h23 = *(const unsigned long long*)&sH[k * 64 + b0 + 2];
                asm("fma.rn.f32x2 %0, %1, %2, %0;" : "+l"(acc01) : "l"(w2), "l"(h01));
                asm("fma.rn.f32x2 %0, %1, %2, %0;" : "+l"(acc23) : "l"(w2), "l"(h23));
            }
        }
        {
            float a0, a1, a2, a3;
            asm("mov.b64 {%0,%1}, %2;" : "=f"(a0), "=f"(a1) : "l"(acc01));
            asm("mov.b64 {%0,%1}, %2;" : "=f"(a2), "=f"(a3) : "l"(acc23));
            sG[jl * 64 + b0 + 0] = a0;
            sG[jl * 64 + b0 + 1] = a1;
            sG[jl * 64 + b0 + 2] = a2;
            sG[jl * 64 + b0 + 3] = a3;
        }
        __syncthreads();

        // finalize: 5 units x 64 batches
        {
            float gi = sG[(0 * 5 + u_l) * 64 + b_f];
            float gf = sG[(1 * 5 + u_l) * 64 + b_f];
            float gg = sG[(2 * 5 + u_l) * 64 + b_f];
            float go = sG[(3 * 5 + u_l) * 64 + b_f];
            float cp = sC[u_l * 64 + b_f];
            float si = 1.f / (1.f + expf(-gi));
            float sf = 1.f / (1.f + expf(-gf));
            float so = 1.f / (1.f + expf(-go));
            float cc = sf * cp + si * tanhf(gg);
            sC[u_l * 64 + b_f] = cc;
            float h = so * tanhf(cc);
            d_hseq[((size_t)(d * Sv + t_x) * Hv + ub5 + u_l) * 64 + b_f] = h;
        }

        // prefetch next X (hidden under barrier)
        if (step + 1 < Sv) {
            const int tn = (d == 0) ? (step + 1) : (Sv - 2 - step);
            const float* __restrict__ Xn = d_Xg + (size_t)(d * Sv + tn) * Bv * G4;
            px0 = Xn[(b0 + 0) * G4 + j];
            px1 = Xn[(b0 + 1) * G4 + j];
            px2 = Xn[(b0 + 2) * G4 + j];
            px3 = Xn[(b0 + 3) * G4 + j];
        }

        // grid barrier over this direction's blocks
        __syncthreads();
        if (tid == 0) {
            __threadfence();
            atomicAdd(&d_barr[d * Sv + step], 1u);
        }
        const unsigned* ctr = &d_barr[d * Sv + step];
        while (ld_acquire(ctr) < nblk) {}
    }
}

// ---------------- assemble text_out ----------------
__global__ void assemble_to() {
    int i = blockIdx.x * 256 + threadIdx.x;
    if (i >= Bv * Sv * H2) return;
    int h = i % H2;
    int bs = i / H2;
    int s = bs % Sv;
    int b = bs / Sv;
    int dsel = (h >= Hv) ? 1 : 0;
    int u = h - dsel * Hv;
    d_to[i] = d_hseq[((size_t)(dsel * Sv + s) * Hv + u) * 64 + b];
}

// ---------------- V = bil_W @ rel_embed^T ----------------
__global__ void vprep(const float* __restrict__ bw, const float* __restrict__ re) {
    int r = blockIdx.x;
    for (int i = threadIdx.x; i < G4; i += 256) {
        float a = 0.f;
#pragma unroll
        for (int jj = 0; jj < RELDv; jj++) a += bw[i * RELDv + jj] * re[r * RELDv + jj];
        d_V[r * G4 + i] = a;
    }
}

// ---------------- relation scores ----------------
__global__ void relscore(const int* __restrict__ head, const int* __restrict__ behead,
                         const int* __restrict__ rel, const float* __restrict__ bilb) {
    int g = blockIdx.x * 8 + (threadIdx.x >> 5);
    int lane = threadIdx.x & 31;
    if (g >= Bv * Rv) return;
    int b = g / Rv;
    int rr = rel[g];
    float dotv = 0.f;
    if (rr != 0) {
        int h1 = head[g], h2 = behead[g];
        const float* __restrict__ n1 = d_to + (size_t)(b * Sv + h1) * H2;
        const float* __restrict__ n2 = d_to + (size_t)(b * Sv + h2) * H2;
        const float* __restrict__ V = d_V + rr * G4;
        for (int i = lane; i < H2; i += 32) dotv += n1[i] * V[i] + n2[i] * V[H2 + i];
    }
#pragma unroll
    for (int o = 16; o; o >>= 1) dotv += __shfl_down_sync(0xffffffffu, dotv, o);
    if (lane == 0) d_score[g] = 1.f / (1.f + expf(-(dotv + bilb[0])));
}

// ---------------- position weights ----------------
__global__ void pwv_kernel() {
    int b = blockIdx.x;
    int s = threadIdx.x;
    float tl = (float)d_tlen[b];
    float al = (float)d_alen[b];
    float l0 = (float)d_llen[b];
    float l1 = l0 + al - 1.f;
    float ctx = tl - al;
    float jf = (float)s;
    float w;
    if (jf < l0) w = 1.f - (l0 - jf) / ctx;
    else if (jf <= l1) w = 0.f;
    else if (jf < tl) w = 1.f - (jf - l1) / ctx;
    else w = 0.f;
    d_pwv[b * Sv + s] = w;
}

// ---------------- sparse GCN apply ----------------
__global__ void gcn_apply(const int* __restrict__ head, const int* __restrict__ behead,
                          const float* __restrict__ bias, float* __restrict__ out) {
    int bs = blockIdx.x;
    int b = bs >> 8;
    int s1 = bs & 255;
    const int* hd = head + b * Rv;
    int L = 0, Rr = Rv;
    while (L < Rr) { int m = (L + Rr) >> 1; if (hd[m] < s1) L = m + 1; else Rr = m; }
    int lo = L;
    Rr = Rv;
    while (L < Rr) { int m = (L + Rr) >> 1; if (hd[m] <= s1) L = m + 1; else Rr = m; }
    int hi = L;
    float den = 1.f;
    for (int r = lo; r < hi; r++) den += d_score[b * Rv + r];
    float inv = 1.f / den;
    for (int h = threadIdx.x; h < H2; h += 128) {
        float a = 0.f;
        for (int r = lo; r < hi; r++)
            a += d_score[b * Rv + r] * d_hid[(size_t)(b * Sv + behead[b * Rv + r]) * H2 + h];
        float v = a * inv + bias[h];
        out[(size_t)(b * Sv + s1) * H2 + h] = fmaxf(v, 0.f);
    }
}

// ---------------- attention ----------------
__global__ void xsum_kernel(const float* __restrict__ x) {
    int b = blockIdx.x;
    int h = threadIdx.x;
    if (h >= H2) return;
    int l0 = d_llen[b];
    int l1 = l0 + d_alen[b] - 1;
    if (l1 > Sv - 1) l1 = Sv - 1;
    float a = 0.f;
    for (int s = l0; s <= l1; s++) a += x[(size_t)(b * Sv + s) * H2 + h];
    d_xsum[b * H2 + h] = a;
}

__global__ void attscore() {
    int g = blockIdx.x * 8 + (threadIdx.x >> 5);
    int lane = threadIdx.x & 31;
    if (g >= Bv * Sv) return;
    int b = g >> 8;
    float a = 0.f;
    for (int i = lane; i < H2; i += 32) a += d_xsum[b * H2 + i] * d_to[(size_t)g * H2 + i];
#pragma unroll
    for (int o = 16; o; o >>= 1) a += __shfl_down_sync(0xffffffffu, a, o);
    if (lane == 0) d_attsc[g] = a;
}

__global__ void softmax_kernel() {
    __shared__ float red[256];
    int b = blockIdx.x;
    int tid = threadIdx.x;
    float v = d_attsc[b * Sv + tid];
    red[tid] = v;
    __syncthreads();
    for (int o = 128; o; o >>= 1) {
        if (tid < o) red[tid] = fmaxf(red[tid], red[tid + o]);
        __syncthreads();
    }
    float smax = red[0];
    __syncthreads();
    float e = expf(v - smax);
    red[tid] = e;
    __syncthreads();
    for (int o = 128; o; o >>= 1) {
        if (tid < o) red[tid] += red[tid + o];
        __syncthreads();
    }
    d_alpha[b * Sv + tid] = e / red[0];
}

__global__ void outvec_kernel() {
    int b = blockIdx.x;
    int h = threadIdx.x;
    if (h >= H2) return;
    float a = 0.f;
    for (int s = 0; s < Sv; s++) a += d_alpha[b * Sv + s] * d_to[(size_t)(b * Sv + s) * H2 + h];
    d_ov[b * H2 + h] = a;
}

__global__ void final_fc(const float* __restrict__ fcW, const float* __restrict__ fcb,
                         float* __restrict__ out) {
    int b = blockIdx.x;
    int p = threadIdx.x >> 5;
    int lane = threadIdx.x & 31;
    if (p >= 3) return;
    float a = 0.f;
    for (int h = lane; h < H2; h += 32) a += d_ov[b * H2 + h] * fcW[h * 3 + p];
#pragma unroll
    for (int o = 16; o; o >>= 1) a += __shfl_down_sync(0xffffffffu, a, o);
    if (lane == 0) out[b * 3 + p] = a + fcb[p];
}

// ---------------- launch ----------------
extern "C" void kernel_launch(void* const* d_in, const int* in_sizes, int n_in,
                              void* d_out, int out_size) {
    const int* text_indices = (const int*)d_in[0];
    const int* aspect_indices = (const int*)d_in[1];
    const int* left_indices = (const int*)d_in[2];
    const int* head_vector = (const int*)d_in[4];
    const int* behead_vector = (const int*)d_in[5];
    const int* relation_vector = (const int*)d_in[6];
    const float* embed_table = (const float*)d_in[7];
    const float* rel_embed = (const float*)d_in[8];
    const float* Wf_ih = (const float*)d_in[9];
    const float* Wf_hh = (const float*)d_in[10];
    const float* bf = (const float*)d_in[11];
    const float* Wb_ih = (const float*)d_in[12];
    const float* Wb_hh = (const float*)d_in[13];
    const float* bb = (const float*)d_in[14];
    const float* bil_W = (const float*)d_in[15];
    const float* bil_b = (const float*)d_in[16];
    const float* gc1_W = (const float*)d_in[17];
    const float* gc1_b = (const float*)d_in[18];
    const float* gc2_W = (const float*)d_in[19];
    const float* gc2_b = (const float*)d_in[20];
    const float* fc_W = (const float*)d_in[21];
    const float* fc_b = (const float*)d_in[22];
    float* out = (float*)d_out;

    float* p_text;  cudaGetSymbolAddress((void**)&p_text, d_text);
    float* p_Xg;    cudaGetSymbolAddress((void**)&p_Xg, d_Xg);
    float* p_to;    cudaGetSymbolAddress((void**)&p_to, d_to);
    float* p_hid;   cudaGetSymbolAddress((void**)&p_hid, d_hid);
    float* p_x1;    cudaGetSymbolAddress((void**)&p_x1, d_x1);

    cudaFuncSetAttribute(lstm_persist, cudaFuncAttributeMaxDynamicSharedMemorySize,
                         LSTM_SMEM_BYTES);

    len_kernel<<<1, 64>>>(text_indices, aspect_indices, left_indices);
    embed_kernel<<<(Bv * Sv * Ev + 255) / 256, 256>>>(text_indices, embed_table);

    {
        dim3 g((G4 + 63) / 64, (Bv * Sv) / 128);
        mma_gemm<1, true, false><<<g, 256>>>(p_text, Wf_ih, bf, p_Xg, Bv * Sv, G4, Ev);
        mma_gemm<1, true, false><<<g, 256>>>(p_text, Wb_ih, bb,
                                             p_Xg + (size_t)Sv * Bv * G4, Bv * Sv, G4, Ev);
    }

    barr_reset<<<1, 512>>>();
    lstm_persist<<<2 * LSTM_BLOCKS_PER_DIR, LSTM_THREADS, LSTM_SMEM_BYTES>>>(Wf_hh, Wb_hh);

    assemble_to<<<(Bv * Sv * H2 + 255) / 256, 256>>>();

    vprep<<<NRELv, 256>>>(bil_W, rel_embed);
    relscore<<<(Bv * Rv) / 8, 256>>>(head_vector, behead_vector, relation_vector, bil_b);

    pwv_kernel<<<Bv, Sv>>>();

    {
        dim3 g((H2 + 63) / 64, (Bv * Sv) / 128);
        mma_gemm<0, false, true><<<g, 256>>>(p_to, gc1_W, nullptr, p_hid, Bv * Sv, H2, H2);
    }
    gcn_apply<<<Bv * Sv, 128>>>(head_vector, behead_vector, gc1_b, p_x1);

    {
        dim3 g((H2 + 63) / 64, (Bv * Sv) / 128);
        mma_gemm<0, false, true><<<g, 256>>>(p_x1, gc2_W, nullptr, p_hid, Bv * Sv, H2, H2);
    }
    gcn_apply<<<Bv * Sv, 128>>>(head_vector, behead_vector, gc2_b, p_x1);

    xsum_kernel<<<Bv, 640>>>(p_x1);
    attscore<<<(Bv * Sv) / 8, 256>>>();
    softmax_kernel<<<Bv, 256>>>();
    outvec_kernel<<<Bv, 640>>>();
    final_fc<<<Bv, 96>>>(fc_W, fc_b, out);

    (void)in_sizes; (void)n_in; (void)out_size;
}

// round 11
// speedup vs baseline: 1.4058x; 1.1097x over previous
#include <cuda_runtime.h>
#include <stdint.h>
#include <math.h>

#define Bv 64
#define Sv 256
#define Ev 300
#define Hv 300
#define H2 600
#define G4 1200
#define Rv 512
#define NRELv 46
#define RELDv 50

#define LSTM_BLOCKS_PER_DIR 60
#define LSTM_THREADS 320

// lstm dynamic smem layout (floats)
#define SH_OFF 0                        // sH [300][64]
#define SW_OFF 19200                    // sW [300][20] (quads of jl 16B-aligned)
#define SG_OFF (19200 + 6000)           // sG [20][64]
#define SC_OFF (SG_OFF + 1280)          // sC [5][64]
#define LSTM_SMEM_BYTES ((SC_OFF + 320) * 4)

// mma gemm tile config
#define ASTR 136
#define BSTR 72

// ---------------- device scratch ----------------
__device__ float d_text[Bv * Sv * Ev];
__device__ float d_Xg[2 * Sv * Bv * G4];
__device__ float d_hseq[2 * Sv * Hv * Bv];
__device__ float d_to[Bv * Sv * H2];
__device__ float d_hid[Bv * Sv * H2];
__device__ float d_x1[Bv * Sv * H2];
__device__ float d_V[NRELv * G4];
__device__ float d_score[Bv * Rv];
__device__ float d_pwv[Bv * Sv];
__device__ float d_xsum[Bv * H2];
__device__ float d_attsc[Bv * Sv];
__device__ float d_alpha[Bv * Sv];
__device__ float d_ov[Bv * H2];
__device__ int d_tlen[Bv], d_alen[Bv], d_llen[Bv];
__device__ unsigned d_barr[2 * Sv];

__device__ __forceinline__ unsigned ld_acquire(const unsigned* p) {
    unsigned v;
    asm volatile("ld.acquire.gpu.global.u32 %0, [%1];" : "=r"(v) : "l"(p) : "memory");
    return v;
}

__device__ __forceinline__ float to_tf32(float x) {
    uint32_t r;
    asm("cvt.rna.tf32.f32 %0, %1;" : "=r"(r) : "f"(x));
    return __uint_as_float(r);
}

// ---------------- barrier reset ----------------
__global__ void barr_reset() {
    int i = threadIdx.x;
    if (i < 2 * Sv) d_barr[i] = 0u;
}

// ---------------- lengths ----------------
__global__ void len_kernel(const int* __restrict__ ti, const int* __restrict__ ai,
                           const int* __restrict__ li) {
    int b = threadIdx.x;
    if (b >= Bv) return;
    int t = 0;
    for (int s = 0; s < Sv; s++) t += (ti[b * Sv + s] != 0);
    int a = 0;
    for (int s = 0; s < 4; s++) a += (ai[b * 4 + s] != 0);
    int l = 0;
    for (int s = 0; s < 64; s++) l += (li[b * 64 + s] != 0);
    d_tlen[b] = t;
    d_alen[b] = a;
    d_llen[b] = l;
}

// ---------------- embedding gather ----------------
__global__ void embed_kernel(const int* __restrict__ idx, const float* __restrict__ emb) {
    int i = blockIdx.x * 256 + threadIdx.x;
    if (i >= Bv * Sv * Ev) return;
    int e = i % Ev;
    int m = i / Ev;
    d_text[i] = emb[idx[m] * Ev + e];
}

// ---------------- tf32 MMA GEMM (R7 proven) ----------------
template <int EPI, bool BT, bool PW>
__global__ void __launch_bounds__(256, 3)
mma_gemm(const float* __restrict__ A, const float* __restrict__ Bm,
         const float* __restrict__ bias, float* __restrict__ C,
         int M, int N, int K) {
    __shared__ float As[16 * ASTR];
    __shared__ float Bs[16 * BSTR];

    const int m0 = blockIdx.y * 128;
    const int n0 = blockIdx.x * 64;
    const int tid = threadIdx.x;
    const int wid = tid >> 5;
    const int lane = tid & 31;
    const int grp = lane >> 2;
    const int tig = lane & 3;
    const int m_base = wid * 16;

    float c[8][4];
#pragma unroll
    for (int n = 0; n < 8; n++)
#pragma unroll
        for (int i = 0; i < 4; i++) c[n][i] = 0.f;

    const int a_m = tid >> 1;
    const int a_k4 = (tid & 1) * 4;
    float pwscale = 1.f;
    if (PW) pwscale = d_pwv[m0 + a_m];

    const int kend = (K + 15) & ~15;

    for (int k0 = 0; k0 < kend; k0 += 16) {
#pragma unroll
        for (int kk2 = 0; kk2 < 16; kk2 += 8) {
            int k = k0 + kk2 + a_k4;
            float4 av = make_float4(0.f, 0.f, 0.f, 0.f);
            if (k < K) av = *(const float4*)&A[(size_t)(m0 + a_m) * K + k];
            if (PW) { av.x *= pwscale; av.y *= pwscale; av.z *= pwscale; av.w *= pwscale; }
            As[(kk2 + a_k4 + 0) * ASTR + a_m] = to_tf32(av.x);
            As[(kk2 + a_k4 + 1) * ASTR + a_m] = to_tf32(av.y);
            As[(kk2 + a_k4 + 2) * ASTR + a_m] = to_tf32(av.z);
            As[(kk2 + a_k4 + 3) * ASTR + a_m] = to_tf32(av.w);
        }
        if (BT) {
            int n_l = tid >> 2;
            int kk = (tid & 3) * 4;
            int row = n0 + n_l;
            int k = k0 + kk;
            float4 bv = make_float4(0.f, 0.f, 0.f, 0.f);
            if (row < N && k < K) bv = *(const float4*)&Bm[(size_t)row * K + k];
            Bs[(kk + 0) * BSTR + n_l] = to_tf32(bv.x);
            Bs[(kk + 1) * BSTR + n_l] = to_tf32(bv.y);
            Bs[(kk + 2) * BSTR + n_l] = to_tf32(bv.z);
            Bs[(kk + 3) * BSTR + n_l] = to_tf32(bv.w);
        } else {
            int kk = tid >> 4;
            int n_l = (tid & 15) * 4;
            int k = k0 + kk;
#pragma unroll
            for (int i = 0; i < 4; i++) {
                int n = n0 + n_l + i;
                float v = (k < K && n < N) ? Bm[(size_t)k * N + n] : 0.f;
                Bs[kk * BSTR + n_l + i] = to_tf32(v);
            }
        }
        __syncthreads();

#pragma unroll
        for (int ksub = 0; ksub < 2; ksub++) {
            const int kb = ksub * 8;
            uint32_t a0 = __float_as_uint(As[(kb + tig) * ASTR + m_base + grp]);
            uint32_t a1 = __float_as_uint(As[(kb + tig) * ASTR + m_base + grp + 8]);
            uint32_t a2 = __float_as_uint(As[(kb + tig + 4) * ASTR + m_base + grp]);
            uint32_t a3 = __float_as_uint(As[(kb + tig + 4) * ASTR + m_base + grp + 8]);
#pragma unroll
            for (int n = 0; n < 8; n++) {
                uint32_t b0 = __float_as_uint(Bs[(kb + tig) * BSTR + n * 8 + grp]);
                uint32_t b1 = __float_as_uint(Bs[(kb + tig + 4) * BSTR + n * 8 + grp]);
                asm volatile(
                    "mma.sync.aligned.m16n8k8.row.col.f32.tf32.tf32.f32 "
                    "{%0,%1,%2,%3}, {%4,%5,%6,%7}, {%8,%9}, {%0,%1,%2,%3};"
                    : "+f"(c[n][0]), "+f"(c[n][1]), "+f"(c[n][2]), "+f"(c[n][3])
                    : "r"(a0), "r"(a1), "r"(a2), "r"(a3), "r"(b0), "r"(b1));
            }
        }
        __syncthreads();
    }

#pragma unroll
    for (int n = 0; n < 8; n++) {
        int col0 = n0 + n * 8 + 2 * tig;
#pragma unroll
        for (int half = 0; half < 2; half++) {
            int row = m0 + m_base + grp + half * 8;
            float v0 = c[n][half * 2 + 0];
            float v1 = c[n][half * 2 + 1];
            if (EPI == 0) {
                float b0 = bias ? bias[col0] : 0.f;
                float b1 = (bias && col0 + 1 < N) ? bias[col0 + 1] : 0.f;
                if (col0 < N) C[(size_t)row * N + col0] = v0 + b0;
                if (col0 + 1 < N) C[(size_t)row * N + col0 + 1] = v1 + b1;
            } else {
                int bb = row >> 8;
                int ss = row & 255;
                size_t base = (size_t)(ss * Bv + bb) * G4;
                if (col0 < N) C[base + col0] = v0 + bias[col0];
                if (col0 + 1 < N) C[base + col0 + 1] = v1 + bias[col0 + 1];
            }
        }
    }
}

// ---------------- persistent BiLSTM: broadcast-friendly thread map ----------------
// thread (jg, b): jg = tid>>6 (0..4) = quad of gate-rows, b = tid&63 (batch).
// Warp = one jg x 32 consecutive batches -> w4 load is a 16B broadcast (1 phase),
// h load is 128B coalesced (1 phase): 2 crossbar phases per k instead of 5.
__global__ void __launch_bounds__(LSTM_THREADS, 1)
lstm_persist(const float* __restrict__ Wfh, const float* __restrict__ Wbh) {
    extern __shared__ float sm[];
    float* sH = sm + SH_OFF;    // [k][b] 300x64
    float* sW = sm + SW_OFF;    // [k][20]
    float* sG = sm + SG_OFF;    // [jl][b]
    float* sC = sm + SC_OFF;    // [u][b]

    const int d = blockIdx.x / LSTM_BLOCKS_PER_DIR;
    const int ub5 = (blockIdx.x % LSTM_BLOCKS_PER_DIR) * 5;
    const float* __restrict__ W = (d == 0) ? Wfh : Wbh;
    const int tid = threadIdx.x;

    for (int idx = tid; idx < 20 * 300; idx += LSTM_THREADS) {
        int jl = idx / 300, k = idx % 300;
        int j = (jl / 5) * 300 + ub5 + (jl % 5);
        sW[k * 20 + jl] = W[j * 300 + k];
    }
    sC[tid] = 0.f;
    __syncthreads();

    const int jg = tid >> 6;        // 0..4 (quad of gate-rows)
    const int b = tid & 63;         // batch
    // global gate-row indices for this thread's 4 rows
    int jrow[4];
#pragma unroll
    for (int i = 0; i < 4; i++) {
        int jl = jg * 4 + i;
        jrow[i] = (jl / 5) * 300 + ub5 + (jl % 5);
    }
    const int u_l = jg;             // finalize: same (u,b) mapping as before (tid>>6, tid&63)
    const int b_f = b;
    const unsigned nblk = (unsigned)LSTM_BLOCKS_PER_DIR;

    float px0, px1, px2, px3;
    {
        const int t0 = (d == 0) ? 0 : (Sv - 1);
        const float* __restrict__ Xb = d_Xg + (size_t)(d * Sv + t0) * Bv * G4 + (size_t)b * G4;
        px0 = Xb[jrow[0]];
        px1 = Xb[jrow[1]];
        px2 = Xb[jrow[2]];
        px3 = Xb[jrow[3]];
    }

    for (int step = 0; step < Sv; step++) {
        const int t_x = (d == 0) ? step : (Sv - 1 - step);

        float acc0 = px0, acc1 = px1, acc2 = px2, acc3 = px3;

        if (step > 0) {
            const int t_hp = (d == 0) ? (step - 1) : (Sv - step);
            const float4* __restrict__ Hp =
                (const float4*)(d_hseq + (size_t)(d * Sv + t_hp) * Hv * Bv);
            float4* sH4 = (float4*)sH;
#pragma unroll
            for (int i = 0; i < 15; i++)
                sH4[tid + i * LSTM_THREADS] = Hp[tid + i * LSTM_THREADS];
            __syncthreads();

            const float* __restrict__ sWq = sW + jg * 4;
#pragma unroll 4
            for (int k = 0; k < 300; k++) {
                float4 w4 = *(const float4*)&sWq[k * 20];
                float hk = sH[k * 64 + b];
                acc0 += w4.x * hk;
                acc1 += w4.y * hk;
                acc2 += w4.z * hk;
                acc3 += w4.w * hk;
            }
        }
        sG[(jg * 4 + 0) * 64 + b] = acc0;
        sG[(jg * 4 + 1) * 64 + b] = acc1;
        sG[(jg * 4 + 2) * 64 + b] = acc2;
        sG[(jg * 4 + 3) * 64 + b] = acc3;
        __syncthreads();

        // finalize: 5 units x 64 batches
        {
            float gi = sG[(0 * 5 + u_l) * 64 + b_f];
            float gf = sG[(1 * 5 + u_l) * 64 + b_f];
            float gg = sG[(2 * 5 + u_l) * 64 + b_f];
            float go = sG[(3 * 5 + u_l) * 64 + b_f];
            float cp = sC[u_l * 64 + b_f];
            float si = 1.f / (1.f + expf(-gi));
            float sf = 1.f / (1.f + expf(-gf));
            float so = 1.f / (1.f + expf(-go));
            float cc = sf * cp + si * tanhf(gg);
            sC[u_l * 64 + b_f] = cc;
            float h = so * tanhf(cc);
            d_hseq[((size_t)(d * Sv + t_x) * Hv + ub5 + u_l) * 64 + b_f] = h;
        }

        // prefetch next X (hidden under barrier)
        if (step + 1 < Sv) {
            const int tn = (d == 0) ? (step + 1) : (Sv - 2 - step);
            const float* __restrict__ Xn =
                d_Xg + (size_t)(d * Sv + tn) * Bv * G4 + (size_t)b * G4;
            px0 = Xn[jrow[0]];
            px1 = Xn[jrow[1]];
            px2 = Xn[jrow[2]];
            px3 = Xn[jrow[3]];
        }

        // grid barrier over this direction's blocks
        __syncthreads();
        if (tid == 0) {
            __threadfence();
            atomicAdd(&d_barr[d * Sv + step], 1u);
        }
        const unsigned* ctr = &d_barr[d * Sv + step];
        while (ld_acquire(ctr) < nblk) {}
    }
}

// ---------------- assemble text_out ----------------
__global__ void assemble_to() {
    int i = blockIdx.x * 256 + threadIdx.x;
    if (i >= Bv * Sv * H2) return;
    int h = i % H2;
    int bs = i / H2;
    int s = bs % Sv;
    int b = bs / Sv;
    int dsel = (h >= Hv) ? 1 : 0;
    int u = h - dsel * Hv;
    d_to[i] = d_hseq[((size_t)(dsel * Sv + s) * Hv + u) * 64 + b];
}

// ---------------- V = bil_W @ rel_embed^T ----------------
__global__ void vprep(const float* __restrict__ bw, const float* __restrict__ re) {
    int r = blockIdx.x;
    for (int i = threadIdx.x; i < G4; i += 256) {
        float a = 0.f;
#pragma unroll
        for (int jj = 0; jj < RELDv; jj++) a += bw[i * RELDv + jj] * re[r * RELDv + jj];
        d_V[r * G4 + i] = a;
    }
}

// ---------------- relation scores ----------------
__global__ void relscore(const int* __restrict__ head, const int* __restrict__ behead,
                         const int* __restrict__ rel, const float* __restrict__ bilb) {
    int g = blockIdx.x * 8 + (threadIdx.x >> 5);
    int lane = threadIdx.x & 31;
    if (g >= Bv * Rv) return;
    int b = g / Rv;
    int rr = rel[g];
    float dotv = 0.f;
    if (rr != 0) {
        int h1 = head[g], h2 = behead[g];
        const float* __restrict__ n1 = d_to + (size_t)(b * Sv + h1) * H2;
        const float* __restrict__ n2 = d_to + (size_t)(b * Sv + h2) * H2;
        const float* __restrict__ V = d_V + rr * G4;
        for (int i = lane; i < H2; i += 32) dotv += n1[i] * V[i] + n2[i] * V[H2 + i];
    }
#pragma unroll
    for (int o = 16; o; o >>= 1) dotv += __shfl_down_sync(0xffffffffu, dotv, o);
    if (lane == 0) d_score[g] = 1.f / (1.f + expf(-(dotv + bilb[0])));
}

// ---------------- position weights ----------------
__global__ void pwv_kernel() {
    int b = blockIdx.x;
    int s = threadIdx.x;
    float tl = (float)d_tlen[b];
    float al = (float)d_alen[b];
    float l0 = (float)d_llen[b];
    float l1 = l0 + al - 1.f;
    float ctx = tl - al;
    float jf = (float)s;
    float w;
    if (jf < l0) w = 1.f - (l0 - jf) / ctx;
    else if (jf <= l1) w = 0.f;
    else if (jf < tl) w = 1.f - (jf - l1) / ctx;
    else w = 0.f;
    d_pwv[b * Sv + s] = w;
}

// ---------------- sparse GCN apply ----------------
__global__ void gcn_apply(const int* __restrict__ head, const int* __restrict__ behead,
                          const float* __restrict__ bias, float* __restrict__ out) {
    int bs = blockIdx.x;
    int b = bs >> 8;
    int s1 = bs & 255;
    const int* hd = head + b * Rv;
    int L = 0, Rr = Rv;
    while (L < Rr) { int m = (L + Rr) >> 1; if (hd[m] < s1) L = m + 1; else Rr = m; }
    int lo = L;
    Rr = Rv;
    while (L < Rr) { int m = (L + Rr) >> 1; if (hd[m] <= s1) L = m + 1; else Rr = m; }
    int hi = L;
    float den = 1.f;
    for (int r = lo; r < hi; r++) den += d_score[b * Rv + r];
    float inv = 1.f / den;
    for (int h = threadIdx.x; h < H2; h += 128) {
        float a = 0.f;
        for (int r = lo; r < hi; r++)
            a += d_score[b * Rv + r] * d_hid[(size_t)(b * Sv + behead[b * Rv + r]) * H2 + h];
        float v = a * inv + bias[h];
        out[(size_t)(b * Sv + s1) * H2 + h] = fmaxf(v, 0.f);
    }
}

// ---------------- attention ----------------
__global__ void xsum_kernel(const float* __restrict__ x) {
    int b = blockIdx.x;
    int h = threadIdx.x;
    if (h >= H2) return;
    int l0 = d_llen[b];
    int l1 = l0 + d_alen[b] - 1;
    if (l1 > Sv - 1) l1 = Sv - 1;
    float a = 0.f;
    for (int s = l0; s <= l1; s++) a += x[(size_t)(b * Sv + s) * H2 + h];
    d_xsum[b * H2 + h] = a;
}

__global__ void attscore() {
    int g = blockIdx.x * 8 + (threadIdx.x >> 5);
    int lane = threadIdx.x & 31;
    if (g >= Bv * Sv) return;
    int b = g >> 8;
    float a = 0.f;
    for (int i = lane; i < H2; i += 32) a += d_xsum[b * H2 + i] * d_to[(size_t)g * H2 + i];
#pragma unroll
    for (int o = 16; o; o >>= 1) a += __shfl_down_sync(0xffffffffu, a, o);
    if (lane == 0) d_attsc[g] = a;
}

__global__ void softmax_kernel() {
    __shared__ float red[256];
    int b = blockIdx.x;
    int tid = threadIdx.x;
    float v = d_attsc[b * Sv + tid];
    red[tid] = v;
    __syncthreads();
    for (int o = 128; o; o >>= 1) {
        if (tid < o) red[tid] = fmaxf(red[tid], red[tid + o]);
        __syncthreads();
    }
    float smax = red[0];
    __syncthreads();
    float e = expf(v - smax);
    red[tid] = e;
    __syncthreads();
    for (int o = 128; o; o >>= 1) {
        if (tid < o) red[tid] += red[tid + o];
        __syncthreads();
    }
    d_alpha[b * Sv + tid] = e / red[0];
}

__global__ void outvec_kernel() {
    int b = blockIdx.x;
    int h = threadIdx.x;
    if (h >= H2) return;
    float a = 0.f;
    for (int s = 0; s < Sv; s++) a += d_alpha[b * Sv + s] * d_to[(size_t)(b * Sv + s) * H2 + h];
    d_ov[b * H2 + h] = a;
}

__global__ void final_fc(const float* __restrict__ fcW, const float* __restrict__ fcb,
                         float* __restrict__ out) {
    int b = blockIdx.x;
    int p = threadIdx.x >> 5;
    int lane = threadIdx.x & 31;
    if (p >= 3) return;
    float a = 0.f;
    for (int h = lane; h < H2; h += 32) a += d_ov[b * H2 + h] * fcW[h * 3 + p];
#pragma unroll
    for (int o = 16; o; o >>= 1) a += __shfl_down_sync(0xffffffffu, a, o);
    if (lane == 0) out[b * 3 + p] = a + fcb[p];
}

// ---------------- launch ----------------
extern "C" void kernel_launch(void* const* d_in, const int* in_sizes, int n_in,
                              void* d_out, int out_size) {
    const int* text_indices = (const int*)d_in[0];
    const int* aspect_indices = (const int*)d_in[1];
    const int* left_indices = (const int*)d_in[2];
    const int* head_vector = (const int*)d_in[4];
    const int* behead_vector = (const int*)d_in[5];
    const int* relation_vector = (const int*)d_in[6];
    const float* embed_table = (const float*)d_in[7];
    const float* rel_embed = (const float*)d_in[8];
    const float* Wf_ih = (const float*)d_in[9];
    const float* Wf_hh = (const float*)d_in[10];
    const float* bf = (const float*)d_in[11];
    const float* Wb_ih = (const float*)d_in[12];
    const float* Wb_hh = (const float*)d_in[13];
    const float* bb = (const float*)d_in[14];
    const float* bil_W = (const float*)d_in[15];
    const float* bil_b = (const float*)d_in[16];
    const float* gc1_W = (const float*)d_in[17];
    const float* gc1_b = (const float*)d_in[18];
    const float* gc2_W = (const float*)d_in[19];
    const float* gc2_b = (const float*)d_in[20];
    const float* fc_W = (const float*)d_in[21];
    const float* fc_b = (const float*)d_in[22];
    float* out = (float*)d_out;

    float* p_text;  cudaGetSymbolAddress((void**)&p_text, d_text);
    float* p_Xg;    cudaGetSymbolAddress((void**)&p_Xg, d_Xg);
    float* p_to;    cudaGetSymbolAddress((void**)&p_to, d_to);
    float* p_hid;   cudaGetSymbolAddress((void**)&p_hid, d_hid);
    float* p_x1;    cudaGetSymbolAddress((void**)&p_x1, d_x1);

    cudaFuncSetAttribute(lstm_persist, cudaFuncAttributeMaxDynamicSharedMemorySize,
                         LSTM_SMEM_BYTES);

    len_kernel<<<1, 64>>>(text_indices, aspect_indices, left_indices);
    embed_kernel<<<(Bv * Sv * Ev + 255) / 256, 256>>>(text_indices, embed_table);

    {
        dim3 g((G4 + 63) / 64, (Bv * Sv) / 128);
        mma_gemm<1, true, false><<<g, 256>>>(p_text, Wf_ih, bf, p_Xg, Bv * Sv, G4, Ev);
        mma_gemm<1, true, false><<<g, 256>>>(p_text, Wb_ih, bb,
                                             p_Xg + (size_t)Sv * Bv * G4, Bv * Sv, G4, Ev);
    }

    barr_reset<<<1, 512>>>();
    lstm_persist<<<2 * LSTM_BLOCKS_PER_DIR, LSTM_THREADS, LSTM_SMEM_BYTES>>>(Wf_hh, Wb_hh);

    assemble_to<<<(Bv * Sv * H2 + 255) / 256, 256>>>();

    vprep<<<NRELv, 256>>>(bil_W, rel_embed);
    relscore<<<(Bv * Rv) / 8, 256>>>(head_vector, behead_vector, relation_vector, bil_b);

    pwv_kernel<<<Bv, Sv>>>();

    {
        dim3 g((H2 + 63) / 64, (Bv * Sv) / 128);
        mma_gemm<0, false, true><<<g, 256>>>(p_to, gc1_W, nullptr, p_hid, Bv * Sv, H2, H2);
    }
    gcn_apply<<<Bv * Sv, 128>>>(head_vector, behead_vector, gc1_b, p_x1);

    {
        dim3 g((H2 + 63) / 64, (Bv * Sv) / 128);
        mma_gemm<0, false, true><<<g, 256>>>(p_x1, gc2_W, nullptr, p_hid, Bv * Sv, H2, H2);
    }
    gcn_apply<<<Bv * Sv, 128>>>(head_vector, behead_vector, gc2_b, p_x1);

    xsum_kernel<<<Bv, 640>>>(p_x1);
    attscore<<<(Bv * Sv) / 8, 256>>>();
    softmax_kernel<<<Bv, 256>>>();
    outvec_kernel<<<Bv, 640>>>();
    final_fc<<<Bv, 96>>>(fc_W, fc_b, out);

    (void)in_sizes; (void)n_in; (void)out_size;
}

// round 12
// speedup vs baseline: 1.5158x; 1.0783x over previous
#include <cuda_runtime.h>
#include <stdint.h>
#include <math.h>

#define Bv 64
#define Sv 256
#define Ev 300
#define Hv 300
#define H2 600
#define G4 1200
#define Rv 512
#define NRELv 46
#define RELDv 50

#define LSTM_BLOCKS_PER_DIR 75   // 4 units per block
#define LSTM_THREADS 256         // (jg 0..3) x (b 0..63)

// lstm dynamic smem layout (floats)
#define SH_OFF 0                        // sH [300][64]
#define SW_OFF 19200                    // sW [300][16]
#define SG_OFF (19200 + 4800)           // sG [16][64]
#define SC_OFF (SG_OFF + 1024)          // sC [4][64]
#define LSTM_SMEM_BYTES ((SC_OFF + 256) * 4)

// mma gemm tile config
#define ASTR 136
#define BSTR 72

// ---------------- device scratch ----------------
__device__ float d_text[Bv * Sv * Ev];
__device__ float d_Xg[2 * Sv * Bv * G4];
__device__ float d_hseq[2 * Sv * Hv * Bv];
__device__ float d_to[Bv * Sv * H2];
__device__ float d_hid[Bv * Sv * H2];
__device__ float d_x1[Bv * Sv * H2];
__device__ float d_V[NRELv * G4];
__device__ float d_score[Bv * Rv];
__device__ float d_pwv[Bv * Sv];
__device__ float d_xsum[Bv * H2];
__device__ float d_attsc[Bv * Sv];
__device__ float d_alpha[Bv * Sv];
__device__ float d_ov[Bv * H2];
__device__ int d_tlen[Bv], d_alen[Bv], d_llen[Bv];
__device__ unsigned d_barr[2 * Sv];

__device__ __forceinline__ unsigned ld_acquire(const unsigned* p) {
    unsigned v;
    asm volatile("ld.acquire.gpu.global.u32 %0, [%1];" : "=r"(v) : "l"(p) : "memory");
    return v;
}

__device__ __forceinline__ float to_tf32(float x) {
    uint32_t r;
    asm("cvt.rna.tf32.f32 %0, %1;" : "=r"(r) : "f"(x));
    return __uint_as_float(r);
}

// ---------------- barrier reset ----------------
__global__ void barr_reset() {
    int i = threadIdx.x;
    if (i < 2 * Sv) d_barr[i] = 0u;
}

// ---------------- lengths ----------------
__global__ void len_kernel(const int* __restrict__ ti, const int* __restrict__ ai,
                           const int* __restrict__ li) {
    int b = threadIdx.x;
    if (b >= Bv) return;
    int t = 0;
    for (int s = 0; s < Sv; s++) t += (ti[b * Sv + s] != 0);
    int a = 0;
    for (int s = 0; s < 4; s++) a += (ai[b * 4 + s] != 0);
    int l = 0;
    for (int s = 0; s < 64; s++) l += (li[b * 64 + s] != 0);
    d_tlen[b] = t;
    d_alen[b] = a;
    d_llen[b] = l;
}

// ---------------- embedding gather ----------------
__global__ void embed_kernel(const int* __restrict__ idx, const float* __restrict__ emb) {
    int i = blockIdx.x * 256 + threadIdx.x;
    if (i >= Bv * Sv * Ev) return;
    int e = i % Ev;
    int m = i / Ev;
    d_text[i] = emb[idx[m] * Ev + e];
}

// ---------------- tf32 MMA GEMM (R7 proven) ----------------
template <int EPI, bool BT, bool PW>
__global__ void __launch_bounds__(256, 3)
mma_gemm(const float* __restrict__ A, const float* __restrict__ Bm,
         const float* __restrict__ bias, float* __restrict__ C,
         int M, int N, int K) {
    __shared__ float As[16 * ASTR];
    __shared__ float Bs[16 * BSTR];

    const int m0 = blockIdx.y * 128;
    const int n0 = blockIdx.x * 64;
    const int tid = threadIdx.x;
    const int wid = tid >> 5;
    const int lane = tid & 31;
    const int grp = lane >> 2;
    const int tig = lane & 3;
    const int m_base = wid * 16;

    float c[8][4];
#pragma unroll
    for (int n = 0; n < 8; n++)
#pragma unroll
        for (int i = 0; i < 4; i++) c[n][i] = 0.f;

    const int a_m = tid >> 1;
    const int a_k4 = (tid & 1) * 4;
    float pwscale = 1.f;
    if (PW) pwscale = d_pwv[m0 + a_m];

    const int kend = (K + 15) & ~15;

    for (int k0 = 0; k0 < kend; k0 += 16) {
#pragma unroll
        for (int kk2 = 0; kk2 < 16; kk2 += 8) {
            int k = k0 + kk2 + a_k4;
            float4 av = make_float4(0.f, 0.f, 0.f, 0.f);
            if (k < K) av = *(const float4*)&A[(size_t)(m0 + a_m) * K + k];
            if (PW) { av.x *= pwscale; av.y *= pwscale; av.z *= pwscale; av.w *= pwscale; }
            As[(kk2 + a_k4 + 0) * ASTR + a_m] = to_tf32(av.x);
            As[(kk2 + a_k4 + 1) * ASTR + a_m] = to_tf32(av.y);
            As[(kk2 + a_k4 + 2) * ASTR + a_m] = to_tf32(av.z);
            As[(kk2 + a_k4 + 3) * ASTR + a_m] = to_tf32(av.w);
        }
        if (BT) {
            int n_l = tid >> 2;
            int kk = (tid & 3) * 4;
            int row = n0 + n_l;
            int k = k0 + kk;
            float4 bv = make_float4(0.f, 0.f, 0.f, 0.f);
            if (row < N && k < K) bv = *(const float4*)&Bm[(size_t)row * K + k];
            Bs[(kk + 0) * BSTR + n_l] = to_tf32(bv.x);
            Bs[(kk + 1) * BSTR + n_l] = to_tf32(bv.y);
            Bs[(kk + 2) * BSTR + n_l] = to_tf32(bv.z);
            Bs[(kk + 3) * BSTR + n_l] = to_tf32(bv.w);
        } else {
            int kk = tid >> 4;
            int n_l = (tid & 15) * 4;
            int k = k0 + kk;
#pragma unroll
            for (int i = 0; i < 4; i++) {
                int n = n0 + n_l + i;
                float v = (k < K && n < N) ? Bm[(size_t)k * N + n] : 0.f;
                Bs[kk * BSTR + n_l + i] = to_tf32(v);
            }
        }
        __syncthreads();

#pragma unroll
        for (int ksub = 0; ksub < 2; ksub++) {
            const int kb = ksub * 8;
            uint32_t a0 = __float_as_uint(As[(kb + tig) * ASTR + m_base + grp]);
            uint32_t a1 = __float_as_uint(As[(kb + tig) * ASTR + m_base + grp + 8]);
            uint32_t a2 = __float_as_uint(As[(kb + tig + 4) * ASTR + m_base + grp]);
            uint32_t a3 = __float_as_uint(As[(kb + tig + 4) * ASTR + m_base + grp + 8]);
#pragma unroll
            for (int n = 0; n < 8; n++) {
                uint32_t b0 = __float_as_uint(Bs[(kb + tig) * BSTR + n * 8 + grp]);
                uint32_t b1 = __float_as_uint(Bs[(kb + tig + 4) * BSTR + n * 8 + grp]);
                asm volatile(
                    "mma.sync.aligned.m16n8k8.row.col.f32.tf32.tf32.f32 "
                    "{%0,%1,%2,%3}, {%4,%5,%6,%7}, {%8,%9}, {%0,%1,%2,%3};"
                    : "+f"(c[n][0]), "+f"(c[n][1]), "+f"(c[n][2]), "+f"(c[n][3])
                    : "r"(a0), "r"(a1), "r"(a2), "r"(a3), "r"(b0), "r"(b1));
            }
        }
        __syncthreads();
    }

#pragma unroll
    for (int n = 0; n < 8; n++) {
        int col0 = n0 + n * 8 + 2 * tig;
#pragma unroll
        for (int half = 0; half < 2; half++) {
            int row = m0 + m_base + grp + half * 8;
            float v0 = c[n][half * 2 + 0];
            float v1 = c[n][half * 2 + 1];
            if (EPI == 0) {
                float b0 = bias ? bias[col0] : 0.f;
                float b1 = (bias && col0 + 1 < N) ? bias[col0 + 1] : 0.f;
                if (col0 < N) C[(size_t)row * N + col0] = v0 + b0;
                if (col0 + 1 < N) C[(size_t)row * N + col0 + 1] = v1 + b1;
            } else {
                int bb = row >> 8;
                int ss = row & 255;
                size_t base = (size_t)(ss * Bv + bb) * G4;
                if (col0 < N) C[base + col0] = v0 + bias[col0];
                if (col0 + 1 < N) C[base + col0 + 1] = v1 + bias[col0 + 1];
            }
        }
    }
}

// ---------------- persistent BiLSTM: 75 blocks/dir x 4 units, tid0-only barrier ----
// thread (jg, b): jg = tid>>6 (0..3) = gate index, b = tid&63 = batch.
// Thread computes rows jl = jg*4 + u (u=0..3): gate jg, units 0..3.
__global__ void __launch_bounds__(LSTM_THREADS, 1)
lstm_persist(const float* __restrict__ Wfh, const float* __restrict__ Wbh) {
    extern __shared__ float sm[];
    float* sH = sm + SH_OFF;    // [k][b] 300x64
    float* sW = sm + SW_OFF;    // [k][16]
    float* sG = sm + SG_OFF;    // [jl][b] 16x64
    float* sC = sm + SC_OFF;    // [u][b] 4x64

    const int d = blockIdx.x / LSTM_BLOCKS_PER_DIR;
    const int ub4 = (blockIdx.x % LSTM_BLOCKS_PER_DIR) * 4;
    const float* __restrict__ W = (d == 0) ? Wfh : Wbh;
    const int tid = threadIdx.x;

    // stage W: rows jl = g*4+u -> global j = g*300 + ub4 + u
    for (int idx = tid; idx < 16 * 300; idx += LSTM_THREADS) {
        int jl = idx / 300, k = idx % 300;
        int g = jl >> 2, u = jl & 3;
        sW[k * 16 + jl] = W[(g * 300 + ub4 + u) * 300 + k];
    }
    sC[tid & 255] = 0.f;
    __syncthreads();

    const int jg = tid >> 6;        // gate 0..3
    const int b = tid & 63;         // batch
    int jrow[4];
#pragma unroll
    for (int u = 0; u < 4; u++) jrow[u] = jg * 300 + ub4 + u;
    const int u_l = tid >> 6;       // finalize: unit 0..3
    const int b_f = tid & 63;
    const unsigned nblk = (unsigned)LSTM_BLOCKS_PER_DIR;

    float px0, px1, px2, px3;
    {
        const int t0 = (d == 0) ? 0 : (Sv - 1);
        const float* __restrict__ Xb =
            d_Xg + (size_t)(d * Sv + t0) * Bv * G4 + (size_t)b * G4;
        px0 = Xb[jrow[0]];
        px1 = Xb[jrow[1]];
        px2 = Xb[jrow[2]];
        px3 = Xb[jrow[3]];
    }

    for (int step = 0; step < Sv; step++) {
        const int t_x = (d == 0) ? step : (Sv - 1 - step);

        float acc0 = px0, acc1 = px1, acc2 = px2, acc3 = px3;

        if (step > 0) {
            const int t_hp = (d == 0) ? (step - 1) : (Sv - step);
            const float4* __restrict__ Hp =
                (const float4*)(d_hseq + (size_t)(d * Sv + t_hp) * Hv * Bv);
            float4* sH4 = (float4*)sH;
            for (int i = tid; i < 4800; i += LSTM_THREADS) sH4[i] = Hp[i];
            __syncthreads();

            const float* __restrict__ sWq = sW + jg * 4;
#pragma unroll 4
            for (int k = 0; k < 300; k++) {
                float4 w4 = *(const float4*)&sWq[k * 16];  // broadcast across warp
                float hk = sH[k * 64 + b];                  // 128B coalesced
                acc0 += w4.x * hk;
                acc1 += w4.y * hk;
                acc2 += w4.z * hk;
                acc3 += w4.w * hk;
            }
        }
        sG[(jg * 4 + 0) * 64 + b] = acc0;
        sG[(jg * 4 + 1) * 64 + b] = acc1;
        sG[(jg * 4 + 2) * 64 + b] = acc2;
        sG[(jg * 4 + 3) * 64 + b] = acc3;
        __syncthreads();

        // finalize: 4 units x 64 batches (rows g*4+u: gate g of unit u)
        {
            float gi = sG[(0 * 4 + u_l) * 64 + b_f];
            float gf = sG[(1 * 4 + u_l) * 64 + b_f];
            float gg = sG[(2 * 4 + u_l) * 64 + b_f];
            float go = sG[(3 * 4 + u_l) * 64 + b_f];
            float cp = sC[u_l * 64 + b_f];
            float si = 1.f / (1.f + expf(-gi));
            float sf = 1.f / (1.f + expf(-gf));
            float so = 1.f / (1.f + expf(-go));
            float cc = sf * cp + si * tanhf(gg);
            sC[u_l * 64 + b_f] = cc;
            float h = so * tanhf(cc);
            d_hseq[((size_t)(d * Sv + t_x) * Hv + ub4 + u_l) * 64 + b_f] = h;
        }

        // prefetch next X (hidden under barrier)
        if (step + 1 < Sv) {
            const int tn = (d == 0) ? (step + 1) : (Sv - 2 - step);
            const float* __restrict__ Xn =
                d_Xg + (size_t)(d * Sv + tn) * Bv * G4 + (size_t)b * G4;
            px0 = Xn[jrow[0]];
            px1 = Xn[jrow[1]];
            px2 = Xn[jrow[2]];
            px3 = Xn[jrow[3]];
        }

        // grid barrier: single poller per block (avoids LTS slice saturation)
        __syncthreads();
        if (tid == 0) {
            __threadfence();
            atomicAdd(&d_barr[d * Sv + step], 1u);
            const unsigned* ctr = &d_barr[d * Sv + step];
            while (ld_acquire(ctr) < nblk) {}
        }
        __syncthreads();
    }
}

// ---------------- assemble text_out ----------------
__global__ void assemble_to() {
    int i = blockIdx.x * 256 + threadIdx.x;
    if (i >= Bv * Sv * H2) return;
    int h = i % H2;
    int bs = i / H2;
    int s = bs % Sv;
    int b = bs / Sv;
    int dsel = (h >= Hv) ? 1 : 0;
    int u = h - dsel * Hv;
    d_to[i] = d_hseq[((size_t)(dsel * Sv + s) * Hv + u) * 64 + b];
}

// ---------------- V = bil_W @ rel_embed^T ----------------
__global__ void vprep(const float* __restrict__ bw, const float* __restrict__ re) {
    int r = blockIdx.x;
    for (int i = threadIdx.x; i < G4; i += 256) {
        float a = 0.f;
#pragma unroll
        for (int jj = 0; jj < RELDv; jj++) a += bw[i * RELDv + jj] * re[r * RELDv + jj];
        d_V[r * G4 + i] = a;
    }
}

// ---------------- relation scores ----------------
__global__ void relscore(const int* __restrict__ head, const int* __restrict__ behead,
                         const int* __restrict__ rel, const float* __restrict__ bilb) {
    int g = blockIdx.x * 8 + (threadIdx.x >> 5);
    int lane = threadIdx.x & 31;
    if (g >= Bv * Rv) return;
    int b = g / Rv;
    int rr = rel[g];
    float dotv = 0.f;
    if (rr != 0) {
        int h1 = head[g], h2 = behead[g];
        const float* __restrict__ n1 = d_to + (size_t)(b * Sv + h1) * H2;
        const float* __restrict__ n2 = d_to + (size_t)(b * Sv + h2) * H2;
        const float* __restrict__ V = d_V + rr * G4;
        for (int i = lane; i < H2; i += 32) dotv += n1[i] * V[i] + n2[i] * V[H2 + i];
    }
#pragma unroll
    for (int o = 16; o; o >>= 1) dotv += __shfl_down_sync(0xffffffffu, dotv, o);
    if (lane == 0) d_score[g] = 1.f / (1.f + expf(-(dotv + bilb[0])));
}

// ---------------- position weights ----------------
__global__ void pwv_kernel() {
    int b = blockIdx.x;
    int s = threadIdx.x;
    float tl = (float)d_tlen[b];
    float al = (float)d_alen[b];
    float l0 = (float)d_llen[b];
    float l1 = l0 + al - 1.f;
    float ctx = tl - al;
    float jf = (float)s;
    float w;
    if (jf < l0) w = 1.f - (l0 - jf) / ctx;
    else if (jf <= l1) w = 0.f;
    else if (jf < tl) w = 1.f - (jf - l1) / ctx;
    else w = 0.f;
    d_pwv[b * Sv + s] = w;
}

// ---------------- sparse GCN apply ----------------
__global__ void gcn_apply(const int* __restrict__ head, const int* __restrict__ behead,
                          const float* __restrict__ bias, float* __restrict__ out) {
    int bs = blockIdx.x;
    int b = bs >> 8;
    int s1 = bs & 255;
    const int* hd = head + b * Rv;
    int L = 0, Rr = Rv;
    while (L < Rr) { int m = (L + Rr) >> 1; if (hd[m] < s1) L = m + 1; else Rr = m; }
    int lo = L;
    Rr = Rv;
    while (L < Rr) { int m = (L + Rr) >> 1; if (hd[m] <= s1) L = m + 1; else Rr = m; }
    int hi = L;
    float den = 1.f;
    for (int r = lo; r < hi; r++) den += d_score[b * Rv + r];
    float inv = 1.f / den;
    for (int h = threadIdx.x; h < H2; h += 128) {
        float a = 0.f;
        for (int r = lo; r < hi; r++)
            a += d_score[b * Rv + r] * d_hid[(size_t)(b * Sv + behead[b * Rv + r]) * H2 + h];
        float v = a * inv + bias[h];
        out[(size_t)(b * Sv + s1) * H2 + h] = fmaxf(v, 0.f);
    }
}

// ---------------- attention ----------------
__global__ void xsum_kernel(const float* __restrict__ x) {
    int b = blockIdx.x;
    int h = threadIdx.x;
    if (h >= H2) return;
    int l0 = d_llen[b];
    int l1 = l0 + d_alen[b] - 1;
    if (l1 > Sv - 1) l1 = Sv - 1;
    float a = 0.f;
    for (int s = l0; s <= l1; s++) a += x[(size_t)(b * Sv + s) * H2 + h];
    d_xsum[b * H2 + h] = a;
}

__global__ void attscore() {
    int g = blockIdx.x * 8 + (threadIdx.x >> 5);
    int lane = threadIdx.x & 31;
    if (g >= Bv * Sv) return;
    int b = g >> 8;
    float a = 0.f;
    for (int i = lane; i < H2; i += 32) a += d_xsum[b * H2 + i] * d_to[(size_t)g * H2 + i];
#pragma unroll
    for (int o = 16; o; o >>= 1) a += __shfl_down_sync(0xffffffffu, a, o);
    if (lane == 0) d_attsc[g] = a;
}

__global__ void softmax_kernel() {
    __shared__ float red[256];
    int b = blockIdx.x;
    int tid = threadIdx.x;
    float v = d_attsc[b * Sv + tid];
    red[tid] = v;
    __syncthreads();
    for (int o = 128; o; o >>= 1) {
        if (tid < o) red[tid] = fmaxf(red[tid], red[tid + o]);
        __syncthreads();
    }
    float smax = red[0];
    __syncthreads();
    float e = expf(v - smax);
    red[tid] = e;
    __syncthreads();
    for (int o = 128; o; o >>= 1) {
        if (tid < o) red[tid] += red[tid + o];
        __syncthreads();
    }
    d_alpha[b * Sv + tid] = e / red[0];
}

__global__ void outvec_kernel() {
    int b = blockIdx.x;
    int h = threadIdx.x;
    if (h >= H2) return;
    float a = 0.f;
    for (int s = 0; s < Sv; s++) a += d_alpha[b * Sv + s] * d_to[(size_t)(b * Sv + s) * H2 + h];
    d_ov[b * H2 + h] = a;
}

__global__ void final_fc(const float* __restrict__ fcW, const float* __restrict__ fcb,
                         float* __restrict__ out) {
    int b = blockIdx.x;
    int p = threadIdx.x >> 5;
    int lane = threadIdx.x & 31;
    if (p >= 3) return;
    float a = 0.f;
    for (int h = lane; h < H2; h += 32) a += d_ov[b * H2 + h] * fcW[h * 3 + p];
#pragma unroll
    for (int o = 16; o; o >>= 1) a += __shfl_down_sync(0xffffffffu, a, o);
    if (lane == 0) out[b * 3 + p] = a + fcb[p];
}

// ---------------- launch ----------------
extern "C" void kernel_launch(void* const* d_in, const int* in_sizes, int n_in,
                              void* d_out, int out_size) {
    const int* text_indices = (const int*)d_in[0];
    const int* aspect_indices = (const int*)d_in[1];
    const int* left_indices = (const int*)d_in[2];
    const int* head_vector = (const int*)d_in[4];
    const int* behead_vector = (const int*)d_in[5];
    const int* relation_vector = (const int*)d_in[6];
    const float* embed_table = (const float*)d_in[7];
    const float* rel_embed = (const float*)d_in[8];
    const float* Wf_ih = (const float*)d_in[9];
    const float* Wf_hh = (const float*)d_in[10];
    const float* bf = (const float*)d_in[11];
    const float* Wb_ih = (const float*)d_in[12];
    const float* Wb_hh = (const float*)d_in[13];
    const float* bb = (const float*)d_in[14];
    const float* bil_W = (const float*)d_in[15];
    const float* bil_b = (const float*)d_in[16];
    const float* gc1_W = (const float*)d_in[17];
    const float* gc1_b = (const float*)d_in[18];
    const float* gc2_W = (const float*)d_in[19];
    const float* gc2_b = (const float*)d_in[20];
    const float* fc_W = (const float*)d_in[21];
    const float* fc_b = (const float*)d_in[22];
    float* out = (float*)d_out;

    float* p_text;  cudaGetSymbolAddress((void**)&p_text, d_text);
    float* p_Xg;    cudaGetSymbolAddress((void**)&p_Xg, d_Xg);
    float* p_to;    cudaGetSymbolAddress((void**)&p_to, d_to);
    float* p_hid;   cudaGetSymbolAddress((void**)&p_hid, d_hid);
    float* p_x1;    cudaGetSymbolAddress((void**)&p_x1, d_x1);

    cudaFuncSetAttribute(lstm_persist, cudaFuncAttributeMaxDynamicSharedMemorySize,
                         LSTM_SMEM_BYTES);

    len_kernel<<<1, 64>>>(text_indices, aspect_indices, left_indices);
    embed_kernel<<<(Bv * Sv * Ev + 255) / 256, 256>>>(text_indices, embed_table);

    {
        dim3 g((G4 + 63) / 64, (Bv * Sv) / 128);
        mma_gemm<1, true, false><<<g, 256>>>(p_text, Wf_ih, bf, p_Xg, Bv * Sv, G4, Ev);
        mma_gemm<1, true, false><<<g, 256>>>(p_text, Wb_ih, bb,
                                             p_Xg + (size_t)Sv * Bv * G4, Bv * Sv, G4, Ev);
    }

    barr_reset<<<1, 512>>>();
    lstm_persist<<<2 * LSTM_BLOCKS_PER_DIR, LSTM_THREADS, LSTM_SMEM_BYTES>>>(Wf_hh, Wb_hh);

    assemble_to<<<(Bv * Sv * H2 + 255) / 256, 256>>>();

    vprep<<<NRELv, 256>>>(bil_W, rel_embed);
    relscore<<<(Bv * Rv) / 8, 256>>>(head_vector, behead_vector, relation_vector, bil_b);

    pwv_kernel<<<Bv, Sv>>>();

    {
        dim3 g((H2 + 63) / 64, (Bv * Sv) / 128);
        mma_gemm<0, false, true><<<g, 256>>>(p_to, gc1_W, nullptr, p_hid, Bv * Sv, H2, H2);
    }
    gcn_apply<<<Bv * Sv, 128>>>(head_vector, behead_vector, gc1_b, p_x1);

    {
        dim3 g((H2 + 63) / 64, (Bv * Sv) / 128);
        mma_gemm<0, false, true><<<g, 256>>>(p_x1, gc2_W, nullptr, p_hid, Bv * Sv, H2, H2);
    }
    gcn_apply<<<Bv * Sv, 128>>>(head_vector, behead_vector, gc2_b, p_x1);

    xsum_kernel<<<Bv, 640>>>(p_x1);
    attscore<<<(Bv * Sv) / 8, 256>>>();
    softmax_kernel<<<Bv, 256>>>();
    outvec_kernel<<<Bv, 640>>>();
    final_fc<<<Bv, 96>>>(fc_W, fc_b, out);

    (void)in_sizes; (void)n_in; (void)out_size;
}

// round 13
// speedup vs baseline: 1.5203x; 1.0030x over previous
#include <cuda_runtime.h>
#include <stdint.h>
#include <math.h>

#define Bv 64
#define Sv 256
#define Ev 300
#define Hv 300
#define H2 600
#define G4 1200
#define Rv 512
#define NRELv 46
#define RELDv 50

#define LSTM_BLOCKS_PER_DIR 75   // 4 units per block
#define LSTM_THREADS 256         // (jg 0..3) x (b 0..63)

// lstm dynamic smem layout (floats)
#define SH_OFF 0                        // sH [300][64]
#define SW_OFF 19200                    // sW [300][16]
#define SG_OFF (19200 + 4800)           // sG [16][64]
#define SC_OFF (SG_OFF + 1024)          // sC [4][64]
#define LSTM_SMEM_BYTES ((SC_OFF + 256) * 4)

// mma gemm tile config
#define ASTR 136
#define BSTR 72

// ---------------- device scratch ----------------
__device__ float d_text[Bv * Sv * Ev];
__device__ float d_Xg[2 * Sv * Bv * G4];
__device__ float d_hseq[2 * Sv * Hv * Bv];
__device__ float d_to[Bv * Sv * H2];
__device__ float d_hid[Bv * Sv * H2];
__device__ float d_x1[Bv * Sv * H2];
__device__ float d_V[NRELv * G4];
__device__ float d_score[Bv * Rv];
__device__ float d_pwv[Bv * Sv];
__device__ float d_xsum[Bv * H2];
__device__ float d_attsc[Bv * Sv];
__device__ float d_alpha[Bv * Sv];
__device__ float d_ov[Bv * H2];
__device__ int d_tlen[Bv], d_alen[Bv], d_llen[Bv];
__device__ unsigned d_barr[2 * Sv];

__device__ __forceinline__ unsigned ld_acquire(const unsigned* p) {
    unsigned v;
    asm volatile("ld.acquire.gpu.global.u32 %0, [%1];" : "=r"(v) : "l"(p) : "memory");
    return v;
}

__device__ __forceinline__ float to_tf32(float x) {
    uint32_t r;
    asm("cvt.rna.tf32.f32 %0, %1;" : "=r"(r) : "f"(x));
    return __uint_as_float(r);
}

// ---------------- barrier reset ----------------
__global__ void barr_reset() {
    int i = threadIdx.x;
    if (i < 2 * Sv) d_barr[i] = 0u;
}

// ---------------- lengths ----------------
__global__ void len_kernel(const int* __restrict__ ti, const int* __restrict__ ai,
                           const int* __restrict__ li) {
    int b = threadIdx.x;
    if (b >= Bv) return;
    int t = 0;
    for (int s = 0; s < Sv; s++) t += (ti[b * Sv + s] != 0);
    int a = 0;
    for (int s = 0; s < 4; s++) a += (ai[b * 4 + s] != 0);
    int l = 0;
    for (int s = 0; s < 64; s++) l += (li[b * 64 + s] != 0);
    d_tlen[b] = t;
    d_alen[b] = a;
    d_llen[b] = l;
}

// ---------------- embedding gather ----------------
__global__ void embed_kernel(const int* __restrict__ idx, const float* __restrict__ emb) {
    int i = blockIdx.x * 256 + threadIdx.x;
    if (i >= Bv * Sv * Ev) return;
    int e = i % Ev;
    int m = i / Ev;
    d_text[i] = emb[idx[m] * Ev + e];
}

// ---------------- tf32 MMA GEMM: 2-stage double-buffered pipeline ----------------
// BT: B is [N,K] row-major (use B^T). else B is [K,N].
// EPI 0: C[m*N+n] (+bias). EPI 1: row m=b*Sv+s -> C[(s*Bv+b)*G4+n] (+bias).
// PW: scale A row m by d_pwv[m] on load.
template <int EPI, bool BT, bool PW>
__global__ void __launch_bounds__(256, 3)
mma_gemm(const float* __restrict__ A, const float* __restrict__ Bm,
         const float* __restrict__ bias, float* __restrict__ C,
         int M, int N, int K) {
    __shared__ float As[2][16 * ASTR];
    __shared__ float Bs[2][16 * BSTR];

    const int m0 = blockIdx.y * 128;
    const int n0 = blockIdx.x * 64;
    const int tid = threadIdx.x;
    const int wid = tid >> 5;
    const int lane = tid & 31;
    const int grp = lane >> 2;
    const int tig = lane & 3;
    const int m_base = wid * 16;

    float c[8][4];
#pragma unroll
    for (int n = 0; n < 8; n++)
#pragma unroll
        for (int i = 0; i < 4; i++) c[n][i] = 0.f;

    const int a_m = tid >> 1;
    const int a_k4 = (tid & 1) * 4;
    float pwscale = 1.f;
    if (PW) pwscale = d_pwv[m0 + a_m];

    // B loader coords
    const int bt_nl = tid >> 2;            // BT: 0..63
    const int bt_kk = (tid & 3) * 4;       // BT: 0,4,8,12
    const int nb_kk = tid >> 4;            // nonBT: 0..15
    const int nb_nl = (tid & 15) * 4;      // nonBT: 0..60

    const int niter = ((K + 15) & ~15) >> 4;

    float4 ra0, ra1;          // A prefetch regs
    float4 rbq;               // B prefetch (BT)
    float rb4[4];             // B prefetch (non-BT)

    // ---- load helpers (registers only) ----
    auto loadG = [&](int it) {
        int k0 = it << 4;
        {
            int k = k0 + a_k4;
            ra0 = make_float4(0.f, 0.f, 0.f, 0.f);
            if (k < K) ra0 = *(const float4*)&A[(size_t)(m0 + a_m) * K + k];
            k = k0 + 8 + a_k4;
            ra1 = make_float4(0.f, 0.f, 0.f, 0.f);
            if (k < K) ra1 = *(const float4*)&A[(size_t)(m0 + a_m) * K + k];
            if (PW) {
                ra0.x *= pwscale; ra0.y *= pwscale; ra0.z *= pwscale; ra0.w *= pwscale;
                ra1.x *= pwscale; ra1.y *= pwscale; ra1.z *= pwscale; ra1.w *= pwscale;
            }
        }
        if (BT) {
            int row = n0 + bt_nl;
            int k = k0 + bt_kk;
            rbq = make_float4(0.f, 0.f, 0.f, 0.f);
            if (row < N && k < K) rbq = *(const float4*)&Bm[(size_t)row * K + k];
        } else {
            int k = k0 + nb_kk;
#pragma unroll
            for (int i = 0; i < 4; i++) {
                int n = n0 + nb_nl + i;
                rb4[i] = (k < K && n < N) ? Bm[(size_t)k * N + n] : 0.f;
            }
        }
    };
    auto storeS = [&](int buf) {
        As[buf][(a_k4 + 0) * ASTR + a_m] = to_tf32(ra0.x);
        As[buf][(a_k4 + 1) * ASTR + a_m] = to_tf32(ra0.y);
        As[buf][(a_k4 + 2) * ASTR + a_m] = to_tf32(ra0.z);
        As[buf][(a_k4 + 3) * ASTR + a_m] = to_tf32(ra0.w);
        As[buf][(8 + a_k4 + 0) * ASTR + a_m] = to_tf32(ra1.x);
        As[buf][(8 + a_k4 + 1) * ASTR + a_m] = to_tf32(ra1.y);
        As[buf][(8 + a_k4 + 2) * ASTR + a_m] = to_tf32(ra1.z);
        As[buf][(8 + a_k4 + 3) * ASTR + a_m] = to_tf32(ra1.w);
        if (BT) {
            Bs[buf][(bt_kk + 0) * BSTR + bt_nl] = to_tf32(rbq.x);
            Bs[buf][(bt_kk + 1) * BSTR + bt_nl] = to_tf32(rbq.y);
            Bs[buf][(bt_kk + 2) * BSTR + bt_nl] = to_tf32(rbq.z);
            Bs[buf][(bt_kk + 3) * BSTR + bt_nl] = to_tf32(rbq.w);
        } else {
#pragma unroll
            for (int i = 0; i < 4; i++)
                Bs[buf][nb_kk * BSTR + nb_nl + i] = to_tf32(rb4[i]);
        }
    };

    // prologue
    loadG(0);
    storeS(0);
    __syncthreads();

    for (int it = 0; it < niter; it++) {
        const int cur = it & 1;
        if (it + 1 < niter) loadG(it + 1);   // long-latency loads issued first

#pragma unroll
        for (int ksub = 0; ksub < 2; ksub++) {
            const int kb = ksub * 8;
            uint32_t a0 = __float_as_uint(As[cur][(kb + tig) * ASTR + m_base + grp]);
            uint32_t a1 = __float_as_uint(As[cur][(kb + tig) * ASTR + m_base + grp + 8]);
            uint32_t a2 = __float_as_uint(As[cur][(kb + tig + 4) * ASTR + m_base + grp]);
            uint32_t a3 = __float_as_uint(As[cur][(kb + tig + 4) * ASTR + m_base + grp + 8]);
#pragma unroll
            for (int n = 0; n < 8; n++) {
                uint32_t b0 = __float_as_uint(Bs[cur][(kb + tig) * BSTR + n * 8 + grp]);
                uint32_t b1 = __float_as_uint(Bs[cur][(kb + tig + 4) * BSTR + n * 8 + grp]);
                asm volatile(
                    "mma.sync.aligned.m16n8k8.row.col.f32.tf32.tf32.f32 "
                    "{%0,%1,%2,%3}, {%4,%5,%6,%7}, {%8,%9}, {%0,%1,%2,%3};"
                    : "+f"(c[n][0]), "+f"(c[n][1]), "+f"(c[n][2]), "+f"(c[n][3])
                    : "r"(a0), "r"(a1), "r"(a2), "r"(a3), "r"(b0), "r"(b1));
            }
        }

        if (it + 1 < niter) storeS(1 - cur);  // write buffer not being read
        __syncthreads();
    }

    // ---- epilogue ----
#pragma unroll
    for (int n = 0; n < 8; n++) {
        int col0 = n0 + n * 8 + 2 * tig;
#pragma unroll
        for (int half = 0; half < 2; half++) {
            int row = m0 + m_base + grp + half * 8;
            float v0 = c[n][half * 2 + 0];
            float v1 = c[n][half * 2 + 1];
            if (EPI == 0) {
                float b0 = bias ? bias[col0] : 0.f;
                float b1 = (bias && col0 + 1 < N) ? bias[col0 + 1] : 0.f;
                if (col0 < N) C[(size_t)row * N + col0] = v0 + b0;
                if (col0 + 1 < N) C[(size_t)row * N + col0 + 1] = v1 + b1;
            } else {
                int bb = row >> 8;
                int ss = row & 255;
                size_t base = (size_t)(ss * Bv + bb) * G4;
                if (col0 < N) C[base + col0] = v0 + bias[col0];
                if (col0 + 1 < N) C[base + col0 + 1] = v1 + bias[col0 + 1];
            }
        }
    }
}

// ---------------- persistent BiLSTM (R12 state) ----------------
__global__ void __launch_bounds__(LSTM_THREADS, 1)
lstm_persist(const float* __restrict__ Wfh, const float* __restrict__ Wbh) {
    extern __shared__ float sm[];
    float* sH = sm + SH_OFF;
    float* sW = sm + SW_OFF;
    float* sG = sm + SG_OFF;
    float* sC = sm + SC_OFF;

    const int d = blockIdx.x / LSTM_BLOCKS_PER_DIR;
    const int ub4 = (blockIdx.x % LSTM_BLOCKS_PER_DIR) * 4;
    const float* __restrict__ W = (d == 0) ? Wfh : Wbh;
    const int tid = threadIdx.x;

    for (int idx = tid; idx < 16 * 300; idx += LSTM_THREADS) {
        int jl = idx / 300, k = idx % 300;
        int g = jl >> 2, u = jl & 3;
        sW[k * 16 + jl] = W[(g * 300 + ub4 + u) * 300 + k];
    }
    sC[tid & 255] = 0.f;
    __syncthreads();

    const int jg = tid >> 6;
    const int b = tid & 63;
    int jrow[4];
#pragma unroll
    for (int u = 0; u < 4; u++) jrow[u] = jg * 300 + ub4 + u;
    const int u_l = tid >> 6;
    const int b_f = tid & 63;
    const unsigned nblk = (unsigned)LSTM_BLOCKS_PER_DIR;

    float px0, px1, px2, px3;
    {
        const int t0 = (d == 0) ? 0 : (Sv - 1);
        const float* __restrict__ Xb =
            d_Xg + (size_t)(d * Sv + t0) * Bv * G4 + (size_t)b * G4;
        px0 = Xb[jrow[0]];
        px1 = Xb[jrow[1]];
        px2 = Xb[jrow[2]];
        px3 = Xb[jrow[3]];
    }

    for (int step = 0; step < Sv; step++) {
        const int t_x = (d == 0) ? step : (Sv - 1 - step);

        float acc0 = px0, acc1 = px1, acc2 = px2, acc3 = px3;

        if (step > 0) {
            const int t_hp = (d == 0) ? (step - 1) : (Sv - step);
            const float4* __restrict__ Hp =
                (const float4*)(d_hseq + (size_t)(d * Sv + t_hp) * Hv * Bv);
            float4* sH4 = (float4*)sH;
            for (int i = tid; i < 4800; i += LSTM_THREADS) sH4[i] = Hp[i];
            __syncthreads();

            const float* __restrict__ sWq = sW + jg * 4;
#pragma unroll 4
            for (int k = 0; k < 300; k++) {
                float4 w4 = *(const float4*)&sWq[k * 16];
                float hk = sH[k * 64 + b];
                acc0 += w4.x * hk;
                acc1 += w4.y * hk;
                acc2 += w4.z * hk;
                acc3 += w4.w * hk;
            }
        }
        sG[(jg * 4 + 0) * 64 + b] = acc0;
        sG[(jg * 4 + 1) * 64 + b] = acc1;
        sG[(jg * 4 + 2) * 64 + b] = acc2;
        sG[(jg * 4 + 3) * 64 + b] = acc3;
        __syncthreads();

        {
            float gi = sG[(0 * 4 + u_l) * 64 + b_f];
            float gf = sG[(1 * 4 + u_l) * 64 + b_f];
            float gg = sG[(2 * 4 + u_l) * 64 + b_f];
            float go = sG[(3 * 4 + u_l) * 64 + b_f];
            float cp = sC[u_l * 64 + b_f];
            float si = 1.f / (1.f + expf(-gi));
            float sf = 1.f / (1.f + expf(-gf));
            float so = 1.f / (1.f + expf(-go));
            float cc = sf * cp + si * tanhf(gg);
            sC[u_l * 64 + b_f] = cc;
            float h = so * tanhf(cc);
            d_hseq[((size_t)(d * Sv + t_x) * Hv + ub4 + u_l) * 64 + b_f] = h;
        }

        if (step + 1 < Sv) {
            const int tn = (d == 0) ? (step + 1) : (Sv - 2 - step);
            const float* __restrict__ Xn =
                d_Xg + (size_t)(d * Sv + tn) * Bv * G4 + (size_t)b * G4;
            px0 = Xn[jrow[0]];
            px1 = Xn[jrow[1]];
            px2 = Xn[jrow[2]];
            px3 = Xn[jrow[3]];
        }

        __syncthreads();
        if (tid == 0) {
            __threadfence();
            atomicAdd(&d_barr[d * Sv + step], 1u);
            const unsigned* ctr = &d_barr[d * Sv + step];
            while (ld_acquire(ctr) < nblk) {}
        }
        __syncthreads();
    }
}

// ---------------- assemble text_out ----------------
__global__ void assemble_to() {
    int i = blockIdx.x * 256 + threadIdx.x;
    if (i >= Bv * Sv * H2) return;
    int h = i % H2;
    int bs = i / H2;
    int s = bs % Sv;
    int b = bs / Sv;
    int dsel = (h >= Hv) ? 1 : 0;
    int u = h - dsel * Hv;
    d_to[i] = d_hseq[((size_t)(dsel * Sv + s) * Hv + u) * 64 + b];
}

// ---------------- V = bil_W @ rel_embed^T ----------------
__global__ void vprep(const float* __restrict__ bw, const float* __restrict__ re) {
    int r = blockIdx.x;
    for (int i = threadIdx.x; i < G4; i += 256) {
        float a = 0.f;
#pragma unroll
        for (int jj = 0; jj < RELDv; jj++) a += bw[i * RELDv + jj] * re[r * RELDv + jj];
        d_V[r * G4 + i] = a;
    }
}

// ---------------- relation scores ----------------
__global__ void relscore(const int* __restrict__ head, const int* __restrict__ behead,
                         const int* __restrict__ rel, const float* __restrict__ bilb) {
    int g = blockIdx.x * 8 + (threadIdx.x >> 5);
    int lane = threadIdx.x & 31;
    if (g >= Bv * Rv) return;
    int b = g / Rv;
    int rr = rel[g];
    float dotv = 0.f;
    if (rr != 0) {
        int h1 = head[g], h2 = behead[g];
        const float* __restrict__ n1 = d_to + (size_t)(b * Sv + h1) * H2;
        const float* __restrict__ n2 = d_to + (size_t)(b * Sv + h2) * H2;
        const float* __restrict__ V = d_V + rr * G4;
        for (int i = lane; i < H2; i += 32) dotv += n1[i] * V[i] + n2[i] * V[H2 + i];
    }
#pragma unroll
    for (int o = 16; o; o >>= 1) dotv += __shfl_down_sync(0xffffffffu, dotv, o);
    if (lane == 0) d_score[g] = 1.f / (1.f + expf(-(dotv + bilb[0])));
}

// ---------------- position weights ----------------
__global__ void pwv_kernel() {
    int b = blockIdx.x;
    int s = threadIdx.x;
    float tl = (float)d_tlen[b];
    float al = (float)d_alen[b];
    float l0 = (float)d_llen[b];
    float l1 = l0 + al - 1.f;
    float ctx = tl - al;
    float jf = (float)s;
    float w;
    if (jf < l0) w = 1.f - (l0 - jf) / ctx;
    else if (jf <= l1) w = 0.f;
    else if (jf < tl) w = 1.f - (jf - l1) / ctx;
    else w = 0.f;
    d_pwv[b * Sv + s] = w;
}

// ---------------- sparse GCN apply ----------------
__global__ void gcn_apply(const int* __restrict__ head, const int* __restrict__ behead,
                          const float* __restrict__ bias, float* __restrict__ out) {
    int bs = blockIdx.x;
    int b = bs >> 8;
    int s1 = bs & 255;
    const int* hd = head + b * Rv;
    int L = 0, Rr = Rv;
    while (L < Rr) { int m = (L + Rr) >> 1; if (hd[m] < s1) L = m + 1; else Rr = m; }
    int lo = L;
    Rr = Rv;
    while (L < Rr) { int m = (L + Rr) >> 1; if (hd[m] <= s1) L = m + 1; else Rr = m; }
    int hi = L;
    float den = 1.f;
    for (int r = lo; r < hi; r++) den += d_score[b * Rv + r];
    float inv = 1.f / den;
    for (int h = threadIdx.x; h < H2; h += 128) {
        float a = 0.f;
        for (int r = lo; r < hi; r++)
            a += d_score[b * Rv + r] * d_hid[(size_t)(b * Sv + behead[b * Rv + r]) * H2 + h];
        float v = a * inv + bias[h];
        out[(size_t)(b * Sv + s1) * H2 + h] = fmaxf(v, 0.f);
    }
}

// ---------------- attention ----------------
__global__ void xsum_kernel(const float* __restrict__ x) {
    int b = blockIdx.x;
    int h = threadIdx.x;
    if (h >= H2) return;
    int l0 = d_llen[b];
    int l1 = l0 + d_alen[b] - 1;
    if (l1 > Sv - 1) l1 = Sv - 1;
    float a = 0.f;
    for (int s = l0; s <= l1; s++) a += x[(size_t)(b * Sv + s) * H2 + h];
    d_xsum[b * H2 + h] = a;
}

__global__ void attscore() {
    int g = blockIdx.x * 8 + (threadIdx.x >> 5);
    int lane = threadIdx.x & 31;
    if (g >= Bv * Sv) return;
    int b = g >> 8;
    float a = 0.f;
    for (int i = lane; i < H2; i += 32) a += d_xsum[b * H2 + i] * d_to[(size_t)g * H2 + i];
#pragma unroll
    for (int o = 16; o; o >>= 1) a += __shfl_down_sync(0xffffffffu, a, o);
    if (lane == 0) d_attsc[g] = a;
}

__global__ void softmax_kernel() {
    __shared__ float red[256];
    int b = blockIdx.x;
    int tid = threadIdx.x;
    float v = d_attsc[b * Sv + tid];
    red[tid] = v;
    __syncthreads();
    for (int o = 128; o; o >>= 1) {
        if (tid < o) red[tid] = fmaxf(red[tid], red[tid + o]);
        __syncthreads();
    }
    float smax = red[0];
    __syncthreads();
    float e = expf(v - smax);
    red[tid] = e;
    __syncthreads();
    for (int o = 128; o; o >>= 1) {
        if (tid < o) red[tid] += red[tid + o];
        __syncthreads();
    }
    d_alpha[b * Sv + tid] = e / red[0];
}

__global__ void outvec_kernel() {
    int b = blockIdx.x;
    int h = threadIdx.x;
    if (h >= H2) return;
    float a = 0.f;
    for (int s = 0; s < Sv; s++) a += d_alpha[b * Sv + s] * d_to[(size_t)(b * Sv + s) * H2 + h];
    d_ov[b * H2 + h] = a;
}

__global__ void final_fc(const float* __restrict__ fcW, const float* __restrict__ fcb,
                         float* __restrict__ out) {
    int b = blockIdx.x;
    int p = threadIdx.x >> 5;
    int lane = threadIdx.x & 31;
    if (p >= 3) return;
    float a = 0.f;
    for (int h = lane; h < H2; h += 32) a += d_ov[b * H2 + h] * fcW[h * 3 + p];
#pragma unroll
    for (int o = 16; o; o >>= 1) a += __shfl_down_sync(0xffffffffu, a, o);
    if (lane == 0) out[b * 3 + p] = a + fcb[p];
}

// ---------------- launch ----------------
extern "C" void kernel_launch(void* const* d_in, const int* in_sizes, int n_in,
                              void* d_out, int out_size) {
    const int* text_indices = (const int*)d_in[0];
    const int* aspect_indices = (const int*)d_in[1];
    const int* left_indices = (const int*)d_in[2];
    const int* head_vector = (const int*)d_in[4];
    const int* behead_vector = (const int*)d_in[5];
    const int* relation_vector = (const int*)d_in[6];
    const float* embed_table = (const float*)d_in[7];
    const float* rel_embed = (const float*)d_in[8];
    const float* Wf_ih = (const float*)d_in[9];
    const float* Wf_hh = (const float*)d_in[10];
    const float* bf = (const float*)d_in[11];
    const float* Wb_ih = (const float*)d_in[12];
    const float* Wb_hh = (const float*)d_in[13];
    const float* bb = (const float*)d_in[14];
    const float* bil_W = (const float*)d_in[15];
    const float* bil_b = (const float*)d_in[16];
    const float* gc1_W = (const float*)d_in[17];
    const float* gc1_b = (const float*)d_in[18];
    const float* gc2_W = (const float*)d_in[19];
    const float* gc2_b = (const float*)d_in[20];
    const float* fc_W = (const float*)d_in[21];
    const float* fc_b = (const float*)d_in[22];
    float* out = (float*)d_out;

    float* p_text;  cudaGetSymbolAddress((void**)&p_text, d_text);
    float* p_Xg;    cudaGetSymbolAddress((void**)&p_Xg, d_Xg);
    float* p_to;    cudaGetSymbolAddress((void**)&p_to, d_to);
    float* p_hid;   cudaGetSymbolAddress((void**)&p_hid, d_hid);
    float* p_x1;    cudaGetSymbolAddress((void**)&p_x1, d_x1);

    cudaFuncSetAttribute(lstm_persist, cudaFuncAttributeMaxDynamicSharedMemorySize,
                         LSTM_SMEM_BYTES);

    len_kernel<<<1, 64>>>(text_indices, aspect_indices, left_indices);
    embed_kernel<<<(Bv * Sv * Ev + 255) / 256, 256>>>(text_indices, embed_table);

    {
        dim3 g((G4 + 63) / 64, (Bv * Sv) / 128);
        mma_gemm<1, true, false><<<g, 256>>>(p_text, Wf_ih, bf, p_Xg, Bv * Sv, G4, Ev);
        mma_gemm<1, true, false><<<g, 256>>>(p_text, Wb_ih, bb,
                                             p_Xg + (size_t)Sv * Bv * G4, Bv * Sv, G4, Ev);
    }

    barr_reset<<<1, 512>>>();
    lstm_persist<<<2 * LSTM_BLOCKS_PER_DIR, LSTM_THREADS, LSTM_SMEM_BYTES>>>(Wf_hh, Wb_hh);

    assemble_to<<<(Bv * Sv * H2 + 255) / 256, 256>>>();

    vprep<<<NRELv, 256>>>(bil_W, rel_embed);
    relscore<<<(Bv * Rv) / 8, 256>>>(head_vector, behead_vector, relation_vector, bil_b);

    pwv_kernel<<<Bv, Sv>>>();

    {
        dim3 g((H2 + 63) / 64, (Bv * Sv) / 128);
        mma_gemm<0, false, true><<<g, 256>>>(p_to, gc1_W, nullptr, p_hid, Bv * Sv, H2, H2);
    }
    gcn_apply<<<Bv * Sv, 128>>>(head_vector, behead_vector, gc1_b, p_x1);

    {
        dim3 g((H2 + 63) / 64, (Bv * Sv) / 128);
        mma_gemm<0, false, true><<<g, 256>>>(p_x1, gc2_W, nullptr, p_hid, Bv * Sv, H2, H2);
    }
    gcn_apply<<<Bv * Sv, 128>>>(head_vector, behead_vector, gc2_b, p_x1);

    xsum_kernel<<<Bv, 640>>>(p_x1);
    attscore<<<(Bv * Sv) / 8, 256>>>();
    softmax_kernel<<<Bv, 256>>>();
    outvec_kernel<<<Bv, 640>>>();
    final_fc<<<Bv, 96>>>(fc_W, fc_b, out);

    (void)in_sizes; (void)n_in; (void)out_size;
}

// round 14
// speedup vs baseline: 1.8452x; 1.2137x over previous
#include <cuda_runtime.h>
#include <stdint.h>
#include <math.h>

#define Bv 64
#define Sv 256
#define Ev 300
#define Hv 300
#define H2 600
#define G4 1200
#define Rv 512
#define NRELv 46
#define RELDv 50

#define LSTM_BLOCKS_PER_DIR 75   // 4 units (16 gate rows) per block
#define LSTM_THREADS 256

// lstm smem (floats)
#define KP 304
#define SHSTR 72                 // sH row stride (banks tig*72+grp distinct; R8-proven)
#define SWSTR 24                 // sW row stride (banks tig*24+grp distinct; R8-proven)
#define SH_OFF 0                              // sH [KP][72]
#define SW_OFF (KP * SHSTR)                   // sW [KP][24]
#define SG_OFF (SW_OFF + KP * SWSTR)          // sG [16][64]
#define SC_OFF (SG_OFF + 1024)                // sC [4][64]
#define LSTM_SMEM_BYTES ((SC_OFF + 256) * 4)

// mma gemm tile config
#define ASTR 136
#define BSTR 72

// ---------------- device scratch ----------------
__device__ float d_text[Bv * Sv * Ev];
__device__ float d_Xg[2 * Sv * Bv * G4];
__device__ float d_hseq[2 * Sv * Hv * Bv];    // fp32 h (for text_out)
__device__ float d_hseq2[2 * Sv * Hv * Bv];   // tf32-rounded h (for recurrence MMA)
__device__ float d_to[Bv * Sv * H2];
__device__ float d_hid[Bv * Sv * H2];
__device__ float d_x1[Bv * Sv * H2];
__device__ float d_V[NRELv * G4];
__device__ float d_score[Bv * Rv];
__device__ float d_pwv[Bv * Sv];
__device__ float d_xsum[Bv * H2];
__device__ float d_attsc[Bv * Sv];
__device__ float d_alpha[Bv * Sv];
__device__ float d_ov[Bv * H2];
__device__ int d_tlen[Bv], d_alen[Bv], d_llen[Bv];
__device__ unsigned d_barr[2 * Sv];

__device__ __forceinline__ unsigned ld_acquire(const unsigned* p) {
    unsigned v;
    asm volatile("ld.acquire.gpu.global.u32 %0, [%1];" : "=r"(v) : "l"(p) : "memory");
    return v;
}

__device__ __forceinline__ float to_tf32(float x) {
    uint32_t r;
    asm("cvt.rna.tf32.f32 %0, %1;" : "=r"(r) : "f"(x));
    return __uint_as_float(r);
}

// ---------------- barrier reset ----------------
__global__ void barr_reset() {
    int i = threadIdx.x;
    if (i < 2 * Sv) d_barr[i] = 0u;
}

// ---------------- lengths ----------------
__global__ void len_kernel(const int* __restrict__ ti, const int* __restrict__ ai,
                           const int* __restrict__ li) {
    int b = threadIdx.x;
    if (b >= Bv) return;
    int t = 0;
    for (int s = 0; s < Sv; s++) t += (ti[b * Sv + s] != 0);
    int a = 0;
    for (int s = 0; s < 4; s++) a += (ai[b * 4 + s] != 0);
    int l = 0;
    for (int s = 0; s < 64; s++) l += (li[b * 64 + s] != 0);
    d_tlen[b] = t;
    d_alen[b] = a;
    d_llen[b] = l;
}

// ---------------- embedding gather ----------------
__global__ void embed_kernel(const int* __restrict__ idx, const float* __restrict__ emb) {
    int i = blockIdx.x * 256 + threadIdx.x;
    if (i >= Bv * Sv * Ev) return;
    int e = i % Ev;
    int m = i / Ev;
    d_text[i] = emb[idx[m] * Ev + e];
}

// ---------------- tf32 MMA GEMM: 2-stage pipeline (R13 proven) ----------------
template <int EPI, bool BT, bool PW>
__global__ void __launch_bounds__(256, 3)
mma_gemm(const float* __restrict__ A, const float* __restrict__ Bm,
         const float* __restrict__ bias, float* __restrict__ C,
         int M, int N, int K) {
    __shared__ float As[2][16 * ASTR];
    __shared__ float Bs[2][16 * BSTR];

    const int m0 = blockIdx.y * 128;
    const int n0 = blockIdx.x * 64;
    const int tid = threadIdx.x;
    const int wid = tid >> 5;
    const int lane = tid & 31;
    const int grp = lane >> 2;
    const int tig = lane & 3;
    const int m_base = wid * 16;

    float c[8][4];
#pragma unroll
    for (int n = 0; n < 8; n++)
#pragma unroll
        for (int i = 0; i < 4; i++) c[n][i] = 0.f;

    const int a_m = tid >> 1;
    const int a_k4 = (tid & 1) * 4;
    float pwscale = 1.f;
    if (PW) pwscale = d_pwv[m0 + a_m];

    const int bt_nl = tid >> 2;
    const int bt_kk = (tid & 3) * 4;
    const int nb_kk = tid >> 4;
    const int nb_nl = (tid & 15) * 4;

    const int niter = ((K + 15) & ~15) >> 4;

    float4 ra0, ra1;
    float4 rbq;
    float rb4[4];

    auto loadG = [&](int it) {
        int k0 = it << 4;
        {
            int k = k0 + a_k4;
            ra0 = make_float4(0.f, 0.f, 0.f, 0.f);
            if (k < K) ra0 = *(const float4*)&A[(size_t)(m0 + a_m) * K + k];
            k = k0 + 8 + a_k4;
            ra1 = make_float4(0.f, 0.f, 0.f, 0.f);
            if (k < K) ra1 = *(const float4*)&A[(size_t)(m0 + a_m) * K + k];
            if (PW) {
                ra0.x *= pwscale; ra0.y *= pwscale; ra0.z *= pwscale; ra0.w *= pwscale;
                ra1.x *= pwscale; ra1.y *= pwscale; ra1.z *= pwscale; ra1.w *= pwscale;
            }
        }
        if (BT) {
            int row = n0 + bt_nl;
            int k = k0 + bt_kk;
            rbq = make_float4(0.f, 0.f, 0.f, 0.f);
            if (row < N && k < K) rbq = *(const float4*)&Bm[(size_t)row * K + k];
        } else {
            int k = k0 + nb_kk;
#pragma unroll
            for (int i = 0; i < 4; i++) {
                int n = n0 + nb_nl + i;
                rb4[i] = (k < K && n < N) ? Bm[(size_t)k * N + n] : 0.f;
            }
        }
    };
    auto storeS = [&](int buf) {
        As[buf][(a_k4 + 0) * ASTR + a_m] = to_tf32(ra0.x);
        As[buf][(a_k4 + 1) * ASTR + a_m] = to_tf32(ra0.y);
        As[buf][(a_k4 + 2) * ASTR + a_m] = to_tf32(ra0.z);
        As[buf][(a_k4 + 3) * ASTR + a_m] = to_tf32(ra0.w);
        As[buf][(8 + a_k4 + 0) * ASTR + a_m] = to_tf32(ra1.x);
        As[buf][(8 + a_k4 + 1) * ASTR + a_m] = to_tf32(ra1.y);
        As[buf][(8 + a_k4 + 2) * ASTR + a_m] = to_tf32(ra1.z);
        As[buf][(8 + a_k4 + 3) * ASTR + a_m] = to_tf32(ra1.w);
        if (BT) {
            Bs[buf][(bt_kk + 0) * BSTR + bt_nl] = to_tf32(rbq.x);
            Bs[buf][(bt_kk + 1) * BSTR + bt_nl] = to_tf32(rbq.y);
            Bs[buf][(bt_kk + 2) * BSTR + bt_nl] = to_tf32(rbq.z);
            Bs[buf][(bt_kk + 3) * BSTR + bt_nl] = to_tf32(rbq.w);
        } else {
#pragma unroll
            for (int i = 0; i < 4; i++)
                Bs[buf][nb_kk * BSTR + nb_nl + i] = to_tf32(rb4[i]);
        }
    };

    loadG(0);
    storeS(0);
    __syncthreads();

    for (int it = 0; it < niter; it++) {
        const int cur = it & 1;
        if (it + 1 < niter) loadG(it + 1);

#pragma unroll
        for (int ksub = 0; ksub < 2; ksub++) {
            const int kb = ksub * 8;
            uint32_t a0 = __float_as_uint(As[cur][(kb + tig) * ASTR + m_base + grp]);
            uint32_t a1 = __float_as_uint(As[cur][(kb + tig) * ASTR + m_base + grp + 8]);
            uint32_t a2 = __float_as_uint(As[cur][(kb + tig + 4) * ASTR + m_base + grp]);
            uint32_t a3 = __float_as_uint(As[cur][(kb + tig + 4) * ASTR + m_base + grp + 8]);
#pragma unroll
            for (int n = 0; n < 8; n++) {
                uint32_t b0 = __float_as_uint(Bs[cur][(kb + tig) * BSTR + n * 8 + grp]);
                uint32_t b1 = __float_as_uint(Bs[cur][(kb + tig + 4) * BSTR + n * 8 + grp]);
                asm volatile(
                    "mma.sync.aligned.m16n8k8.row.col.f32.tf32.tf32.f32 "
                    "{%0,%1,%2,%3}, {%4,%5,%6,%7}, {%8,%9}, {%0,%1,%2,%3};"
                    : "+f"(c[n][0]), "+f"(c[n][1]), "+f"(c[n][2]), "+f"(c[n][3])
                    : "r"(a0), "r"(a1), "r"(a2), "r"(a3), "r"(b0), "r"(b1));
            }
        }

        if (it + 1 < niter) storeS(1 - cur);
        __syncthreads();
    }

#pragma unroll
    for (int n = 0; n < 8; n++) {
        int col0 = n0 + n * 8 + 2 * tig;
#pragma unroll
        for (int half = 0; half < 2; half++) {
            int row = m0 + m_base + grp + half * 8;
            float v0 = c[n][half * 2 + 0];
            float v1 = c[n][half * 2 + 1];
            if (EPI == 0) {
                float b0 = bias ? bias[col0] : 0.f;
                float b1 = (bias && col0 + 1 < N) ? bias[col0 + 1] : 0.f;
                if (col0 < N) C[(size_t)row * N + col0] = v0 + b0;
                if (col0 + 1 < N) C[(size_t)row * N + col0 + 1] = v1 + b1;
            } else {
                int bb = row >> 8;
                int ss = row & 255;
                size_t base = (size_t)(ss * Bv + bb) * G4;
                if (col0 < N) C[base + col0] = v0 + bias[col0];
                if (col0 + 1 < N) C[base + col0 + 1] = v1 + bias[col0 + 1];
            }
        }
    }
}

// ---------------- persistent BiLSTM: tf32 MMA recurrence, tid0 barrier ----------------
// 150 blocks (75/dir), 256 thr = 8 warps. MMA: M=64 batches (4 m-tiles x 16),
// N=16 gate rows (2 n-tiles x 8), K=304. h for recurrence read from d_hseq2
// (pre-rounded tf32 by producer) -> copy loop is pure float4 traffic.
__global__ void __launch_bounds__(LSTM_THREADS, 1)
lstm_persist(const float* __restrict__ Wfh, const float* __restrict__ Wbh) {
    extern __shared__ float sm[];
    float* sH = sm + SH_OFF;   // [KP][SHSTR]  A operand (batch-major)
    float* sW = sm + SW_OFF;   // [KP][SWSTR]  B operand (16 rows used)
    float* sG = sm + SG_OFF;   // [16][64] gate preacts
    float* sC = sm + SC_OFF;   // [4][64] cell state

    const int d = blockIdx.x / LSTM_BLOCKS_PER_DIR;
    const int ub4 = (blockIdx.x % LSTM_BLOCKS_PER_DIR) * 4;
    const float* __restrict__ W = (d == 0) ? Wfh : Wbh;
    const int tid = threadIdx.x;
    const int wid = tid >> 5;
    const int lane = tid & 31;
    const int grp = lane >> 2;
    const int tig = lane & 3;

    // stage W (tf32), zero pads; zero sH pad rows (NaN x 0 guard)
    for (int idx = tid; idx < KP * SWSTR; idx += LSTM_THREADS) {
        int k = idx / SWSTR, jl = idx % SWSTR;
        float v = 0.f;
        if (jl < 16 && k < 300) {
            int g = jl >> 2, u = jl & 3;
            v = to_tf32(W[(g * 300 + ub4 + u) * 300 + k]);
        }
        sW[k * SWSTR + jl] = v;
    }
    for (int idx = tid; idx < 4 * SHSTR; idx += LSTM_THREADS) sH[300 * SHSTR + idx] = 0.f;
    sC[tid] = 0.f;   // tid<256 == 4*64
    __syncthreads();

    const int jg = tid >> 6;        // gate 0..3 (X-store / finalize map)
    const int b = tid & 63;
    int jrow[4];
#pragma unroll
    for (int u = 0; u < 4; u++) jrow[u] = jg * 300 + ub4 + u;
    const int u_l = tid >> 6;
    const int b_f = tid & 63;
    const unsigned nblk = (unsigned)LSTM_BLOCKS_PER_DIR;

    // mma warp tile coords
    const int m_b = (wid & 3) * 16;       // batch tile
    const int n_b = (wid >> 2) * 8;       // gate-row tile

    float px0, px1, px2, px3;
    {
        const int t0 = (d == 0) ? 0 : (Sv - 1);
        const float* __restrict__ Xb =
            d_Xg + (size_t)(d * Sv + t0) * Bv * G4 + (size_t)b * G4;
        px0 = Xb[jrow[0]];
        px1 = Xb[jrow[1]];
        px2 = Xb[jrow[2]];
        px3 = Xb[jrow[3]];
    }

    for (int step = 0; step < Sv; step++) {
        const int t_x = (d == 0) ? step : (Sv - 1 - step);

        // 1. X preacts into sG
        sG[(jg * 4 + 0) * 64 + b] = px0;
        sG[(jg * 4 + 1) * 64 + b] = px1;
        sG[(jg * 4 + 2) * 64 + b] = px2;
        sG[(jg * 4 + 3) * 64 + b] = px3;

        // 2. copy tf32 h_prev -> sH (pure float4 stream, no cvt)
        if (step > 0) {
            const int t_hp = (d == 0) ? (step - 1) : (Sv - step);
            const float4* __restrict__ Hp =
                (const float4*)(d_hseq2 + (size_t)(d * Sv + t_hp) * Hv * Bv);
            for (int i = tid; i < 4800; i += LSTM_THREADS) {
                int k = i >> 4;
                int b4 = (i & 15) * 4;
                *(float4*)&sH[k * SHSTR + b4] = Hp[i];
            }
        }
        __syncthreads();

        // 3. MMA: sG += h_prev @ W^T (warp-disjoint accumulate)
        if (step > 0) {
            float c0 = 0.f, c1 = 0.f, c2 = 0.f, c3 = 0.f;
#pragma unroll 2
            for (int kb = 0; kb < KP; kb += 8) {
                uint32_t a0 = __float_as_uint(sH[(kb + tig) * SHSTR + m_b + grp]);
                uint32_t a1 = __float_as_uint(sH[(kb + tig) * SHSTR + m_b + grp + 8]);
                uint32_t a2 = __float_as_uint(sH[(kb + tig + 4) * SHSTR + m_b + grp]);
                uint32_t a3 = __float_as_uint(sH[(kb + tig + 4) * SHSTR + m_b + grp + 8]);
                uint32_t bb0 = __float_as_uint(sW[(kb + tig) * SWSTR + n_b + grp]);
                uint32_t bb1 = __float_as_uint(sW[(kb + tig + 4) * SWSTR + n_b + grp]);
                asm volatile(
                    "mma.sync.aligned.m16n8k8.row.col.f32.tf32.tf32.f32 "
                    "{%0,%1,%2,%3}, {%4,%5,%6,%7}, {%8,%9}, {%0,%1,%2,%3};"
                    : "+f"(c0), "+f"(c1), "+f"(c2), "+f"(c3)
                    : "r"(a0), "r"(a1), "r"(a2), "r"(a3), "r"(bb0), "r"(bb1));
            }
            int nn = n_b + 2 * tig;
            sG[nn * 64 + m_b + grp] += c0;
            sG[(nn + 1) * 64 + m_b + grp] += c1;
            sG[nn * 64 + m_b + grp + 8] += c2;
            sG[(nn + 1) * 64 + m_b + grp + 8] += c3;
        }
        __syncthreads();

        // 4. finalize: 4 units x 64 batches; write fp32 h + tf32 h
        {
            float gi = sG[(0 * 4 + u_l) * 64 + b_f];
            float gf = sG[(1 * 4 + u_l) * 64 + b_f];
            float gg = sG[(2 * 4 + u_l) * 64 + b_f];
            float go = sG[(3 * 4 + u_l) * 64 + b_f];
            float cp = sC[u_l * 64 + b_f];
            float si = 1.f / (1.f + expf(-gi));
            float sf = 1.f / (1.f + expf(-gf));
            float so = 1.f / (1.f + expf(-go));
            float cc = sf * cp + si * tanhf(gg);
            sC[u_l * 64 + b_f] = cc;
            float h = so * tanhf(cc);
            size_t off = ((size_t)(d * Sv + t_x) * Hv + ub4 + u_l) * 64 + b_f;
            d_hseq[off] = h;
            d_hseq2[off] = to_tf32(h);
        }

        // 5. prefetch next X
        if (step + 1 < Sv) {
            const int tn = (d == 0) ? (step + 1) : (Sv - 2 - step);
            const float* __restrict__ Xn =
                d_Xg + (size_t)(d * Sv + tn) * Bv * G4 + (size_t)b * G4;
            px0 = Xn[jrow[0]];
            px1 = Xn[jrow[1]];
            px2 = Xn[jrow[2]];
            px3 = Xn[jrow[3]];
        }

        // 6. grid barrier (tid0-only arrive+poll)
        __syncthreads();
        if (tid == 0) {
            __threadfence();
            atomicAdd(&d_barr[d * Sv + step], 1u);
            const unsigned* ctr = &d_barr[d * Sv + step];
            while (ld_acquire(ctr) < nblk) {}
        }
        __syncthreads();
    }
}

// ---------------- assemble text_out ----------------
__global__ void assemble_to() {
    int i = blockIdx.x * 256 + threadIdx.x;
    if (i >= Bv * Sv * H2) return;
    int h = i % H2;
    int bs = i / H2;
    int s = bs % Sv;
    int b = bs / Sv;
    int dsel = (h >= Hv) ? 1 : 0;
    int u = h - dsel * Hv;
    d_to[i] = d_hseq[((size_t)(dsel * Sv + s) * Hv + u) * 64 + b];
}

// ---------------- V = bil_W @ rel_embed^T ----------------
__global__ void vprep(const float* __restrict__ bw, const float* __restrict__ re) {
    int r = blockIdx.x;
    for (int i = threadIdx.x; i < G4; i += 256) {
        float a = 0.f;
#pragma unroll
        for (int jj = 0; jj < RELDv; jj++) a += bw[i * RELDv + jj] * re[r * RELDv + jj];
        d_V[r * G4 + i] = a;
    }
}

// ---------------- relation scores ----------------
__global__ void relscore(const int* __restrict__ head, const int* __restrict__ behead,
                         const int* __restrict__ rel, const float* __restrict__ bilb) {
    int g = blockIdx.x * 8 + (threadIdx.x >> 5);
    int lane = threadIdx.x & 31;
    if (g >= Bv * Rv) return;
    int b = g / Rv;
    int rr = rel[g];
    float dotv = 0.f;
    if (rr != 0) {
        int h1 = head[g], h2 = behead[g];
        const float* __restrict__ n1 = d_to + (size_t)(b * Sv + h1) * H2;
        const float* __restrict__ n2 = d_to + (size_t)(b * Sv + h2) * H2;
        const float* __restrict__ V = d_V + rr * G4;
        for (int i = lane; i < H2; i += 32) dotv += n1[i] * V[i] + n2[i] * V[H2 + i];
    }
#pragma unroll
    for (int o = 16; o; o >>= 1) dotv += __shfl_down_sync(0xffffffffu, dotv, o);
    if (lane == 0) d_score[g] = 1.f / (1.f + expf(-(dotv + bilb[0])));
}

// ---------------- position weights ----------------
__global__ void pwv_kernel() {
    int b = blockIdx.x;
    int s = threadIdx.x;
    float tl = (float)d_tlen[b];
    float al = (float)d_alen[b];
    float l0 = (float)d_llen[b];
    float l1 = l0 + al - 1.f;
    float ctx = tl - al;
    float jf = (float)s;
    float w;
    if (jf < l0) w = 1.f - (l0 - jf) / ctx;
    else if (jf <= l1) w = 0.f;
    else if (jf < tl) w = 1.f - (jf - l1) / ctx;
    else w = 0.f;
    d_pwv[b * Sv + s] = w;
}

// ---------------- sparse GCN apply ----------------
__global__ void gcn_apply(const int* __restrict__ head, const int* __restrict__ behead,
                          const float* __restrict__ bias, float* __restrict__ out) {
    int bs = blockIdx.x;
    int b = bs >> 8;
    int s1 = bs & 255;
    const int* hd = head + b * Rv;
    int L = 0, Rr = Rv;
    while (L < Rr) { int m = (L + Rr) >> 1; if (hd[m] < s1) L = m + 1; else Rr = m; }
    int lo = L;
    Rr = Rv;
    while (L < Rr) { int m = (L + Rr) >> 1; if (hd[m] <= s1) L = m + 1; else Rr = m; }
    int hi = L;
    float den = 1.f;
    for (int r = lo; r < hi; r++) den += d_score[b * Rv + r];
    float inv = 1.f / den;
    for (int h = threadIdx.x; h < H2; h += 128) {
        float a = 0.f;
        for (int r = lo; r < hi; r++)
            a += d_score[b * Rv + r] * d_hid[(size_t)(b * Sv + behead[b * Rv + r]) * H2 + h];
        float v = a * inv + bias[h];
        out[(size_t)(b * Sv + s1) * H2 + h] = fmaxf(v, 0.f);
    }
}

// ---------------- attention ----------------
__global__ void xsum_kernel(const float* __restrict__ x) {
    int b = blockIdx.x;
    int h = threadIdx.x;
    if (h >= H2) return;
    int l0 = d_llen[b];
    int l1 = l0 + d_alen[b] - 1;
    if (l1 > Sv - 1) l1 = Sv - 1;
    float a = 0.f;
    for (int s = l0; s <= l1; s++) a += x[(size_t)(b * Sv + s) * H2 + h];
    d_xsum[b * H2 + h] = a;
}

__global__ void attscore() {
    int g = blockIdx.x * 8 + (threadIdx.x >> 5);
    int lane = threadIdx.x & 31;
    if (g >= Bv * Sv) return;
    int b = g >> 8;
    float a = 0.f;
    for (int i = lane; i < H2; i += 32) a += d_xsum[b * H2 + i] * d_to[(size_t)g * H2 + i];
#pragma unroll
    for (int o = 16; o; o >>= 1) a += __shfl_down_sync(0xffffffffu, a, o);
    if (lane == 0) d_attsc[g] = a;
}

__global__ void softmax_kernel() {
    __shared__ float red[256];
    int b = blockIdx.x;
    int tid = threadIdx.x;
    float v = d_attsc[b * Sv + tid];
    red[tid] = v;
    __syncthreads();
    for (int o = 128; o; o >>= 1) {
        if (tid < o) red[tid] = fmaxf(red[tid], red[tid + o]);
        __syncthreads();
    }
    float smax = red[0];
    __syncthreads();
    float e = expf(v - smax);
    red[tid] = e;
    __syncthreads();
    for (int o = 128; o; o >>= 1) {
        if (tid < o) red[tid] += red[tid + o];
        __syncthreads();
    }
    d_alpha[b * Sv + tid] = e / red[0];
}

__global__ void outvec_kernel() {
    int b = blockIdx.x;
    int h = threadIdx.x;
    if (h >= H2) return;
    float a = 0.f;
    for (int s = 0; s < Sv; s++) a += d_alpha[b * Sv + s] * d_to[(size_t)(b * Sv + s) * H2 + h];
    d_ov[b * H2 + h] = a;
}

__global__ void final_fc(const float* __restrict__ fcW, const float* __restrict__ fcb,
                         float* __restrict__ out) {
    int b = blockIdx.x;
    int p = threadIdx.x >> 5;
    int lane = threadIdx.x & 31;
    if (p >= 3) return;
    float a = 0.f;
    for (int h = lane; h < H2; h += 32) a += d_ov[b * H2 + h] * fcW[h * 3 + p];
#pragma unroll
    for (int o = 16; o; o >>= 1) a += __shfl_down_sync(0xffffffffu, a, o);
    if (lane == 0) out[b * 3 + p] = a + fcb[p];
}

// ---------------- launch ----------------
extern "C" void kernel_launch(void* const* d_in, const int* in_sizes, int n_in,
                              void* d_out, int out_size) {
    const int* text_indices = (const int*)d_in[0];
    const int* aspect_indices = (const int*)d_in[1];
    const int* left_indices = (const int*)d_in[2];
    const int* head_vector = (const int*)d_in[4];
    const int* behead_vector = (const int*)d_in[5];
    const int* relation_vector = (const int*)d_in[6];
    const float* embed_table = (const float*)d_in[7];
    const float* rel_embed = (const float*)d_in[8];
    const float* Wf_ih = (const float*)d_in[9];
    const float* Wf_hh = (const float*)d_in[10];
    const float* bf = (const float*)d_in[11];
    const float* Wb_ih = (const float*)d_in[12];
    const float* Wb_hh = (const float*)d_in[13];
    const float* bb = (const float*)d_in[14];
    const float* bil_W = (const float*)d_in[15];
    const float* bil_b = (const float*)d_in[16];
    const float* gc1_W = (const float*)d_in[17];
    const float* gc1_b = (const float*)d_in[18];
    const float* gc2_W = (const float*)d_in[19];
    const float* gc2_b = (const float*)d_in[20];
    const float* fc_W = (const float*)d_in[21];
    const float* fc_b = (const float*)d_in[22];
    float* out = (float*)d_out;

    float* p_text;  cudaGetSymbolAddress((void**)&p_text, d_text);
    float* p_Xg;    cudaGetSymbolAddress((void**)&p_Xg, d_Xg);
    float* p_to;    cudaGetSymbolAddress((void**)&p_to, d_to);
    float* p_hid;   cudaGetSymbolAddress((void**)&p_hid, d_hid);
    float* p_x1;    cudaGetSymbolAddress((void**)&p_x1, d_x1);

    cudaFuncSetAttribute(lstm_persist, cudaFuncAttributeMaxDynamicSharedMemorySize,
                         LSTM_SMEM_BYTES);

    len_kernel<<<1, 64>>>(text_indices, aspect_indices, left_indices);
    embed_kernel<<<(Bv * Sv * Ev + 255) / 256, 256>>>(text_indices, embed_table);

    {
        dim3 g((G4 + 63) / 64, (Bv * Sv) / 128);
        mma_gemm<1, true, false><<<g, 256>>>(p_text, Wf_ih, bf, p_Xg, Bv * Sv, G4, Ev);
        mma_gemm<1, true, false><<<g, 256>>>(p_text, Wb_ih, bb,
                                             p_Xg + (size_t)Sv * Bv * G4, Bv * Sv, G4, Ev);
    }

    barr_reset<<<1, 512>>>();
    lstm_persist<<<2 * LSTM_BLOCKS_PER_DIR, LSTM_THREADS, LSTM_SMEM_BYTES>>>(Wf_hh, Wb_hh);

    assemble_to<<<(Bv * Sv * H2 + 255) / 256, 256>>>();

    vprep<<<NRELv, 256>>>(bil_W, rel_embed);
    relscore<<<(Bv * Rv) / 8, 256>>>(head_vector, behead_vector, relation_vector, bil_b);

    pwv_kernel<<<Bv, Sv>>>();

    {
        dim3 g((H2 + 63) / 64, (Bv * Sv) / 128);
        mma_gemm<0, false, true><<<g, 256>>>(p_to, gc1_W, nullptr, p_hid, Bv * Sv, H2, H2);
    }
    gcn_apply<<<Bv * Sv, 128>>>(head_vector, behead_vector, gc1_b, p_x1);

    {
        dim3 g((H2 + 63) / 64, (Bv * Sv) / 128);
        mma_gemm<0, false, true><<<g, 256>>>(p_x1, gc2_W, nullptr, p_hid, Bv * Sv, H2, H2);
    }
    gcn_apply<<<Bv * Sv, 128>>>(head_vector, behead_vector, gc2_b, p_x1);

    xsum_kernel<<<Bv, 640>>>(p_x1);
    attscore<<<(Bv * Sv) / 8, 256>>>();
    softmax_kernel<<<Bv, 256>>>();
    outvec_kernel<<<Bv, 640>>>();
    final_fc<<<Bv, 96>>>(fc_W, fc_b, out);

    (void)in_sizes; (void)n_in; (void)out_size;
}